// round 11
// baseline (speedup 1.0000x reference)
#include <cuda_runtime.h>
#include <cuda_bf16.h>
#include <cstddef>
#include <cstdint>

#define NMAX   50000
#define EMAX   800000
#define HDIM   256
#define H4     (HDIM / 4)
#define SCAN_B 256

// ---------------- scratch (device globals) ----------------
__device__ __align__(16) __nv_bfloat16 g_tb[(size_t)NMAX * HDIM];  // GEMM output (bf16 messages)
__device__ __align__(16) __nv_bfloat16 g_yb[(size_t)NMAX * HDIM];  // layer-1 activations (bf16)
__device__ __align__(16) __nv_bfloat16 g_xb[(size_t)NMAX * 128];   // input features (bf16)
__device__ float g_dinv[NMAX];
__device__ int   g_degi[NMAX];
__device__ int   g_off [NMAX + 1];
__device__ int   g_cur [NMAX];
__device__ __align__(8) int2 g_epack[EMAX];   // {src, coef-as-int}
__device__ int   g_part[512];
__device__ float g_gv  [HDIM];
// bf16 split weights, transposed to [n][k]
__device__ __align__(16) __nv_bfloat16 g_w1t_hi[HDIM * 128];
__device__ __align__(16) __nv_bfloat16 g_w1t_lo[HDIM * 128];
__device__ __align__(16) __nv_bfloat16 g_w2t_hi[HDIM * HDIM];
__device__ __align__(16) __nv_bfloat16 g_w2t_lo[HDIM * HDIM];

// ---------------- side stream + events (created once at load; not device allocs) ---
struct SideStream {
    cudaStream_t s;
    cudaEvent_t  fork, join;
    SideStream() {
        cudaStreamCreateWithFlags(&s, cudaStreamNonBlocking);
        cudaEventCreateWithFlags(&fork, cudaEventDisableTiming);
        cudaEventCreateWithFlags(&join, cudaEventDisableTiming);
    }
};
static SideStream g_side;

// ---------------- helpers ----------------
__device__ __forceinline__ uint32_t smem_u32(const void* p) {
    uint32_t a;
    asm("{ .reg .u64 t; cvta.to.shared.u64 t, %1; cvt.u32.u64 %0, t; }" : "=r"(a) : "l"(p));
    return a;
}
#define SWZ(off) ((off) ^ (((off) >> 3) & 0x70))

__device__ __forceinline__ void cp16(uint32_t dst, const void* src) {
    asm volatile("cp.async.cg.shared.global [%0], [%1], 16;" :: "r"(dst), "l"(src));
}
#define CP_COMMIT() asm volatile("cp.async.commit_group;" ::: "memory")

__device__ __forceinline__ void ldsm_x4(uint32_t addr, uint32_t& r0, uint32_t& r1,
                                        uint32_t& r2, uint32_t& r3) {
    asm volatile("ldmatrix.sync.aligned.m8n8.x4.shared.b16 {%0,%1,%2,%3}, [%4];"
                 : "=r"(r0), "=r"(r1), "=r"(r2), "=r"(r3) : "r"(addr));
}

__device__ __forceinline__ void mma_bf16(float* d, const uint32_t* a, const uint32_t* b) {
    asm volatile("mma.sync.aligned.m16n8k16.row.col.f32.bf16.bf16.f32 "
                 "{%0,%1,%2,%3}, {%4,%5,%6,%7}, {%8,%9}, {%0,%1,%2,%3};"
                 : "+f"(d[0]), "+f"(d[1]), "+f"(d[2]), "+f"(d[3])
                 : "r"(a[0]), "r"(a[1]), "r"(a[2]), "r"(a[3]), "r"(b[0]), "r"(b[1]));
}

// bf16x8 (uint4) -> 8x fma into acc
__device__ __forceinline__ void acc8(float* acc, uint4 v, float c) {
    float2 f0 = __bfloat1622float2(*reinterpret_cast<__nv_bfloat162*>(&v.x));
    float2 f1 = __bfloat1622float2(*reinterpret_cast<__nv_bfloat162*>(&v.y));
    float2 f2 = __bfloat1622float2(*reinterpret_cast<__nv_bfloat162*>(&v.z));
    float2 f3 = __bfloat1622float2(*reinterpret_cast<__nv_bfloat162*>(&v.w));
    acc[0] = fmaf(c, f0.x, acc[0]); acc[1] = fmaf(c, f0.y, acc[1]);
    acc[2] = fmaf(c, f1.x, acc[2]); acc[3] = fmaf(c, f1.y, acc[3]);
    acc[4] = fmaf(c, f2.x, acc[4]); acc[5] = fmaf(c, f2.y, acc[5]);
    acc[6] = fmaf(c, f3.x, acc[6]); acc[7] = fmaf(c, f3.y, acc[7]);
}

// node aggregation core: returns post-ReLU 8-value slice for node d (cols lane*8..lane*8+7)
__device__ __forceinline__ void node_aggregate(int d, int lane, const float* __restrict__ b,
                                               float* r) {
    const int beg = g_off[d];
    const int end = g_off[d + 1];
    const uint4* __restrict__ T = reinterpret_cast<const uint4*>(g_tb);
    const int2*  __restrict__ P = g_epack;

    float acc[8] = {0.f, 0.f, 0.f, 0.f, 0.f, 0.f, 0.f, 0.f};

    int e = beg;
#pragma unroll 1
    for (; e + 4 <= end; e += 4) {
        int2 p0 = __ldg(P + e + 0);
        int2 p1 = __ldg(P + e + 1);
        int2 p2 = __ldg(P + e + 2);
        int2 p3 = __ldg(P + e + 3);
        uint4 v0 = __ldg(T + (size_t)p0.x * 32 + lane);
        uint4 v1 = __ldg(T + (size_t)p1.x * 32 + lane);
        uint4 v2 = __ldg(T + (size_t)p2.x * 32 + lane);
        uint4 v3 = __ldg(T + (size_t)p3.x * 32 + lane);
        acc8(acc, v0, __int_as_float(p0.y));
        acc8(acc, v1, __int_as_float(p1.y));
        acc8(acc, v2, __int_as_float(p2.y));
        acc8(acc, v3, __int_as_float(p3.y));
    }
    for (; e < end; e++) {
        int2 p = __ldg(P + e);
        uint4 v = __ldg(T + (size_t)p.x * 32 + lane);
        acc8(acc, v, __int_as_float(p.y));
    }

    const float dd = g_dinv[d];
    acc8(acc, __ldg(T + (size_t)d * 32 + lane), dd * dd);

    const float4* bp = reinterpret_cast<const float4*>(b) + lane * 2;
    float4 b0 = __ldg(bp);
    float4 b1 = __ldg(bp + 1);
    r[0] = fmaxf(acc[0] + b0.x, 0.0f);
    r[1] = fmaxf(acc[1] + b0.y, 0.0f);
    r[2] = fmaxf(acc[2] + b0.z, 0.0f);
    r[3] = fmaxf(acc[3] + b0.w, 0.0f);
    r[4] = fmaxf(acc[4] + b1.x, 0.0f);
    r[5] = fmaxf(acc[5] + b1.y, 0.0f);
    r[6] = fmaxf(acc[6] + b1.z, 0.0f);
    r[7] = fmaxf(acc[7] + b1.w, 0.0f);
}

// ---------------- fused conversions: xconv + wtrans(W1) + wtrans(W2) + zero gv ----
__global__ void convall_kernel(const float* __restrict__ x,
                               const float* __restrict__ W1,
                               const float* __restrict__ W2, int n)
{
    const int idx = blockIdx.x * 256 + threadIdx.x;
    if (idx < HDIM * 128) {
        int nn = idx >> 7, kk = idx & 127;
        float w = W1[(size_t)kk * HDIM + nn];
        __nv_bfloat16 h = __float2bfloat16_rn(w);
        g_w1t_hi[idx] = h;
        g_w1t_lo[idx] = __float2bfloat16_rn(w - __bfloat162float(h));
    }
    if (idx < HDIM * HDIM) {
        int nn = idx >> 8, kk = idx & 255;
        float w = W2[(size_t)kk * HDIM + nn];
        __nv_bfloat16 h = __float2bfloat16_rn(w);
        g_w2t_hi[idx] = h;
        g_w2t_lo[idx] = __float2bfloat16_rn(w - __bfloat162float(h));
    }
    if (idx < HDIM) g_gv[idx] = 0.0f;
    if (idx < n * 32) {
        float4 v = reinterpret_cast<const float4*>(x)[idx];
        __nv_bfloat162 p0 = __float22bfloat162_rn(make_float2(v.x, v.y));
        __nv_bfloat162 p1 = __float22bfloat162_rn(make_float2(v.z, v.w));
        uint2 u;
        u.x = *reinterpret_cast<uint32_t*>(&p0);
        u.y = *reinterpret_cast<uint32_t*>(&p1);
        reinterpret_cast<uint2*>(g_xb)[idx] = u;
    }
}

// ---------------- CSR-build chain (side stream) ----------------
__global__ void prep_kernel(int n)
{
    int i = blockIdx.x * blockDim.x + threadIdx.x;
    if (i < n) g_degi[i] = 0;
}

__global__ void deg_kernel(const int* __restrict__ dst, int E)
{
    int e = blockIdx.x * blockDim.x + threadIdx.x;
    if (e < E) atomicAdd(&g_degi[dst[e]], 1);
}

__global__ void scan1_kernel(int n)
{
    __shared__ int s[SCAN_B];
    int i = blockIdx.x * SCAN_B + threadIdx.x;
    int deg = (i < n) ? g_degi[i] : 0;
    if (i < n) g_dinv[i] = rsqrtf((float)deg + 1.0f);
    s[threadIdx.x] = deg;
    __syncthreads();
    for (int ofs = SCAN_B / 2; ofs > 0; ofs >>= 1) {
        if (threadIdx.x < ofs) s[threadIdx.x] += s[threadIdx.x + ofs];
        __syncthreads();
    }
    if (threadIdx.x == 0) g_part[blockIdx.x] = s[0];
}

__global__ void scan2_kernel(int nblocks, int n, int E)
{
    __shared__ int a[512], b[512];
    int t = threadIdx.x;
    int v = (t < nblocks) ? g_part[t] : 0;
    a[t] = v;
    __syncthreads();
    int* pin = a; int* pout = b;
    for (int ofs = 1; ofs < 512; ofs <<= 1) {
        pout[t] = (t >= ofs) ? pin[t] + pin[t - ofs] : pin[t];
        __syncthreads();
        int* tmp = pin; pin = pout; pout = tmp;
    }
    g_part[t] = (t == 0) ? 0 : pin[t - 1];
    if (t == 0) g_off[n] = E;
}

__global__ void scan3_kernel(int n)
{
    __shared__ int a[SCAN_B], b[SCAN_B];
    int t = threadIdx.x;
    int i = blockIdx.x * SCAN_B + t;
    int v = (i < n) ? g_degi[i] : 0;
    a[t] = v;
    __syncthreads();
    int* pin = a; int* pout = b;
    for (int ofs = 1; ofs < SCAN_B; ofs <<= 1) {
        pout[t] = (t >= ofs) ? pin[t] + pin[t - ofs] : pin[t];
        __syncthreads();
        int* tmp = pin; pin = pout; pout = tmp;
    }
    if (i < n) {
        int excl = (t == 0) ? 0 : pin[t - 1];
        int off = g_part[blockIdx.x] + excl;
        g_off[i] = off;
        g_cur[i] = off;
    }
}

__global__ void scatter_kernel(const int* __restrict__ src, const int* __restrict__ dst, int E)
{
    int e = blockIdx.x * blockDim.x + threadIdx.x;
    if (e < E) {
        int s = src[e];
        int d = dst[e];
        float coef = __ldg(&g_dinv[s]) * __ldg(&g_dinv[d]);
        int pos = atomicAdd(&g_cur[d], 1);
        g_epack[pos] = make_int2(s, __float_as_int(coef));
    }
}

// ---------------- HMMA GEMM v4: C_bf16[M,256] = A_bf16[M,K] @ W[K,256] ----------------
#define ST_A   0
#define ST_BH  16384
#define ST_BL  49152
#define STAGE  81920
#define SM_TOTAL (2 * STAGE)

__global__ __launch_bounds__(512, 1)
void tgemm_kernel(const __nv_bfloat16* __restrict__ A,
                  const __nv_bfloat16* __restrict__ WHI,
                  const __nv_bfloat16* __restrict__ WLO,
                  __nv_bfloat16* __restrict__ C, int M, int K)
{
    extern __shared__ char smem[];
    const uint32_t sb = smem_u32(smem);
    const int tid = threadIdx.x;
    const int wid = tid >> 5;
    const int lane = tid & 31;
    const int warp_m = wid & 3;
    const int warp_n = wid >> 2;
    const int row0 = blockIdx.x * 128;

    float acc[2][8][4];
#pragma unroll
    for (int mt = 0; mt < 2; mt++)
#pragma unroll
        for (int nt = 0; nt < 8; nt++)
#pragma unroll
            for (int q = 0; q < 4; q++) acc[mt][nt][q] = 0.0f;

    const int lr   = lane & 7;
    const int lsel = lane >> 3;
    const int nch  = K >> 6;

    auto stage_load = [&](int c, int buf) {
        const int k0 = c << 6;
        const uint32_t base = sb + buf * STAGE;
#pragma unroll
        for (int i = 0; i < 2; i++) {
            const int idx = tid + (i << 9);
            const int row = idx >> 3;
            const int u   = idx & 7;
            const int grow = min(row0 + row, M - 1);
            cp16(base + ST_A + SWZ(row * 128 + u * 16),
                 A + (size_t)grow * K + k0 + u * 8);
        }
#pragma unroll
        for (int i = 0; i < 4; i++) {
            const int idx = tid + (i << 9);
            const int nr = idx >> 3;
            const int u  = idx & 7;
            const uint32_t sw = SWZ(nr * 128 + u * 16);
            cp16(base + ST_BH + sw, WHI + (size_t)nr * K + k0 + u * 8);
            cp16(base + ST_BL + sw, WLO + (size_t)nr * K + k0 + u * 8);
        }
        CP_COMMIT();
    };

    stage_load(0, 0);

    for (int c = 0; c < nch; c++) {
        if (c + 1 < nch) {
            stage_load(c + 1, (c + 1) & 1);
            asm volatile("cp.async.wait_group 1;" ::: "memory");
        } else {
            asm volatile("cp.async.wait_group 0;" ::: "memory");
        }
        __syncthreads();

        const uint32_t bufb = sb + (c & 1) * STAGE;
#pragma unroll
        for (int kk = 0; kk < 4; kk++) {
            const int kb = kk * 32 + (lsel & 2) * 8;
            uint32_t ah[8];
#pragma unroll
            for (int mt = 0; mt < 2; mt++) {
                const int arow = warp_m * 32 + mt * 16 + (lsel & 1) * 8 + lr;
                const uint32_t aoff = SWZ(arow * 128 + kb);
                ldsm_x4(bufb + ST_A + aoff, ah[mt*4+0], ah[mt*4+1], ah[mt*4+2], ah[mt*4+3]);
            }
            uint32_t bh[16], bl[16];
#pragma unroll
            for (int p = 0; p < 4; p++) {
                const int brow = warp_n * 64 + p * 16 + (lsel >> 1) * 8 + lr;
                const uint32_t boff = SWZ(brow * 128 + kk * 32 + (lsel & 1) * 16);
                ldsm_x4(bufb + ST_BH + boff, bh[p*4+0], bh[p*4+1], bh[p*4+2], bh[p*4+3]);
                ldsm_x4(bufb + ST_BL + boff, bl[p*4+0], bl[p*4+1], bl[p*4+2], bl[p*4+3]);
            }
#pragma unroll
            for (int mt = 0; mt < 2; mt++) {
#pragma unroll
                for (int nt = 0; nt < 8; nt++) {
                    mma_bf16(acc[mt][nt], &ah[mt*4], &bh[nt*2]);
                    mma_bf16(acc[mt][nt], &ah[mt*4], &bl[nt*2]);
                }
            }
        }
        __syncthreads();
    }

    const int tr = lane >> 2;
    const int tc = (lane & 3) * 2;
#pragma unroll
    for (int mt = 0; mt < 2; mt++) {
#pragma unroll
        for (int nt = 0; nt < 8; nt++) {
            const int col = warp_n * 64 + nt * 8 + tc;
            const int r0 = row0 + warp_m * 32 + mt * 16 + tr;
            if (r0 < M) {
                __nv_bfloat162 v = __float22bfloat162_rn(make_float2(acc[mt][nt][0], acc[mt][nt][1]));
                *reinterpret_cast<__nv_bfloat162*>(C + (size_t)r0 * HDIM + col) = v;
            }
            if (r0 + 8 < M) {
                __nv_bfloat162 v = __float22bfloat162_rn(make_float2(acc[mt][nt][2], acc[mt][nt][3]));
                *reinterpret_cast<__nv_bfloat162*>(C + (size_t)(r0 + 8) * HDIM + col) = v;
            }
        }
    }
}

// ---------------- pull layer-1: writes y (bf16) ----------------
__global__ __launch_bounds__(256)
void pull_kernel(const float* __restrict__ b, int n)
{
    const int wid  = threadIdx.x >> 5;
    const int lane = threadIdx.x & 31;
    const int d    = blockIdx.x * 8 + wid;
    if (d >= n) return;

    float r[8];
    node_aggregate(d, lane, b, r);

    __nv_bfloat162 o0 = __float22bfloat162_rn(make_float2(r[0], r[1]));
    __nv_bfloat162 o1 = __float22bfloat162_rn(make_float2(r[2], r[3]));
    __nv_bfloat162 o2 = __float22bfloat162_rn(make_float2(r[4], r[5]));
    __nv_bfloat162 o3 = __float22bfloat162_rn(make_float2(r[6], r[7]));
    uint4 o;
    o.x = *reinterpret_cast<uint32_t*>(&o0);
    o.y = *reinterpret_cast<uint32_t*>(&o1);
    o.z = *reinterpret_cast<uint32_t*>(&o2);
    o.w = *reinterpret_cast<uint32_t*>(&o3);
    reinterpret_cast<uint4*>(g_yb)[(size_t)d * 32 + lane] = o;
}

// ---------------- pull layer-2 fused with mean-pool column sums ----------------
__global__ __launch_bounds__(256)
void pull_sum_kernel(const float* __restrict__ b, int n)
{
    __shared__ float sacc[HDIM];
    const int tid  = threadIdx.x;
    const int wid  = tid >> 5;
    const int lane = tid & 31;
    const int d    = blockIdx.x * 8 + wid;

    sacc[tid] = 0.0f;
    __syncthreads();

    if (d < n) {
        float r[8];
        node_aggregate(d, lane, b, r);
#pragma unroll
        for (int j = 0; j < 8; j++)
            atomicAdd(&sacc[lane * 8 + j], r[j]);
    }
    __syncthreads();
    atomicAdd(&g_gv[tid], sacc[tid]);
}

// ---------------- final linear ----------------
__global__ void final_kernel(const float* __restrict__ Wl, const float* __restrict__ bl,
                             float* __restrict__ out, float invN)
{
    __shared__ float s[2];
    if (threadIdx.x < 2) s[threadIdx.x] = 0.0f;
    __syncthreads();
    const int j = threadIdx.x;
    const float gj = g_gv[j] * invN;
    atomicAdd(&s[0], gj * Wl[j * 2 + 0]);
    atomicAdd(&s[1], gj * Wl[j * 2 + 1]);
    __syncthreads();
    if (threadIdx.x < 2) out[threadIdx.x] = s[threadIdx.x] + bl[threadIdx.x];
}

// ---------------- launcher ----------------
extern "C" void kernel_launch(void* const* d_in, const int* in_sizes, int n_in,
                              void* d_out, int out_size)
{
    const float* x  = (const float*)d_in[0];
    const int*   ei = (const int*)  d_in[1];
    const float* W1 = (const float*)d_in[3];
    const float* b1 = (const float*)d_in[4];
    const float* W2 = (const float*)d_in[5];
    const float* b2 = (const float*)d_in[6];
    const float* Wl = (const float*)d_in[7];
    const float* bl = (const float*)d_in[8];
    float* out = (float*)d_out;

    const int n = in_sizes[0] / 128;   // 50000
    const int E = in_sizes[1] / 2;     // 800000

    const int* src = ei;
    const int* dst = ei + E;

    __nv_bfloat16 *tb_ptr, *yb_ptr, *xb_ptr;
    cudaGetSymbolAddress((void**)&tb_ptr, g_tb);
    cudaGetSymbolAddress((void**)&yb_ptr, g_yb);
    cudaGetSymbolAddress((void**)&xb_ptr, g_xb);
    __nv_bfloat16 *w1h, *w1l, *w2h, *w2l;
    cudaGetSymbolAddress((void**)&w1h, g_w1t_hi);
    cudaGetSymbolAddress((void**)&w1l, g_w1t_lo);
    cudaGetSymbolAddress((void**)&w2h, g_w2t_hi);
    cudaGetSymbolAddress((void**)&w2l, g_w2t_lo);

    cudaFuncSetAttribute(tgemm_kernel, cudaFuncAttributeMaxDynamicSharedMemorySize, SM_TOTAL);

    const int nScanBlocks = (n + SCAN_B - 1) / SCAN_B;
    const int gemmBlocks = (n + 127) / 128;   // 391
    const int pullBlocks = (n + 7) / 8;       // 6250

    // ---- fork: CSR build on side stream, conversions + GEMM1 on main ----
    cudaEventRecord(g_side.fork, 0);
    cudaStreamWaitEvent(g_side.s, g_side.fork, 0);

    prep_kernel   <<<(n + 255) / 256, 256, 0, g_side.s>>>(n);
    deg_kernel    <<<(E + 255) / 256, 256, 0, g_side.s>>>(dst, E);
    scan1_kernel  <<<nScanBlocks, SCAN_B, 0, g_side.s>>>(n);
    scan2_kernel  <<<1, 512, 0, g_side.s>>>(nScanBlocks, n, E);
    scan3_kernel  <<<nScanBlocks, SCAN_B, 0, g_side.s>>>(n);
    scatter_kernel<<<(E + 255) / 256, 256, 0, g_side.s>>>(src, dst, E);
    cudaEventRecord(g_side.join, g_side.s);

    // main stream: conversions + GEMM1
    convall_kernel<<<(n * 32 + 255) / 256, 256>>>(x, W1, W2, n);
    tgemm_kernel<<<gemmBlocks, 512, SM_TOTAL>>>(xb_ptr, w1h, w1l, tb_ptr, n, 128);

    // join: pull1 needs CSR
    cudaStreamWaitEvent(0, g_side.join, 0);

    pull_kernel<<<pullBlocks, 256>>>(b1, n);
    tgemm_kernel<<<gemmBlocks, 512, SM_TOTAL>>>(yb_ptr, w2h, w2l, tb_ptr, n, HDIM);
    pull_sum_kernel<<<pullBlocks, 256>>>(b2, n);

    final_kernel<<<1, HDIM>>>(Wl, bl, out, 1.0f / (float)n);
}

// round 12
// speedup vs baseline: 1.1640x; 1.1640x over previous
#include <cuda_runtime.h>
#include <cuda_bf16.h>
#include <cstddef>
#include <cstdint>

#define NMAX   50000
#define EMAX   800000
#define HDIM   256
#define H4     (HDIM / 4)
#define SCAN_B 256
#define PS_BLOCKS 1184   // pull_sum grid (2 resident waves @ 4 blocks/SM)

// ---------------- scratch (device globals) ----------------
__device__ __align__(16) __nv_bfloat16 g_tb[(size_t)NMAX * HDIM];  // GEMM output (bf16 messages)
__device__ __align__(16) __nv_bfloat16 g_yb[(size_t)NMAX * HDIM];  // layer-1 activations (bf16)
__device__ __align__(16) __nv_bfloat16 g_xb[(size_t)NMAX * 128];   // input features (bf16)
__device__ float g_dinv[NMAX];
__device__ int   g_degi[NMAX];
__device__ int   g_off [NMAX + 1];
__device__ int   g_cur [NMAX];
__device__ __align__(8) int2 g_epack[EMAX];   // {src, coef-as-int}
__device__ int   g_part[512];
__device__ float g_gv  [HDIM];
// bf16 split weights, transposed to [n][k]
__device__ __align__(16) __nv_bfloat16 g_w1t_hi[HDIM * 128];
__device__ __align__(16) __nv_bfloat16 g_w1t_lo[HDIM * 128];
__device__ __align__(16) __nv_bfloat16 g_w2t_hi[HDIM * HDIM];
__device__ __align__(16) __nv_bfloat16 g_w2t_lo[HDIM * HDIM];

// ---------------- side stream + events (created once at load; not device allocs) ---
struct SideStream {
    cudaStream_t s;
    cudaEvent_t  fork, join;
    SideStream() {
        cudaStreamCreateWithFlags(&s, cudaStreamNonBlocking);
        cudaEventCreateWithFlags(&fork, cudaEventDisableTiming);
        cudaEventCreateWithFlags(&join, cudaEventDisableTiming);
    }
};
static SideStream g_side;

// ---------------- helpers ----------------
__device__ __forceinline__ uint32_t smem_u32(const void* p) {
    uint32_t a;
    asm("{ .reg .u64 t; cvta.to.shared.u64 t, %1; cvt.u32.u64 %0, t; }" : "=r"(a) : "l"(p));
    return a;
}
#define SWZ(off) ((off) ^ (((off) >> 3) & 0x70))

__device__ __forceinline__ void cp16(uint32_t dst, const void* src) {
    asm volatile("cp.async.cg.shared.global [%0], [%1], 16;" :: "r"(dst), "l"(src));
}
#define CP_COMMIT() asm volatile("cp.async.commit_group;" ::: "memory")

__device__ __forceinline__ void ldsm_x4(uint32_t addr, uint32_t& r0, uint32_t& r1,
                                        uint32_t& r2, uint32_t& r3) {
    asm volatile("ldmatrix.sync.aligned.m8n8.x4.shared.b16 {%0,%1,%2,%3}, [%4];"
                 : "=r"(r0), "=r"(r1), "=r"(r2), "=r"(r3) : "r"(addr));
}

__device__ __forceinline__ void mma_bf16(float* d, const uint32_t* a, const uint32_t* b) {
    asm volatile("mma.sync.aligned.m16n8k16.row.col.f32.bf16.bf16.f32 "
                 "{%0,%1,%2,%3}, {%4,%5,%6,%7}, {%8,%9}, {%0,%1,%2,%3};"
                 : "+f"(d[0]), "+f"(d[1]), "+f"(d[2]), "+f"(d[3])
                 : "r"(a[0]), "r"(a[1]), "r"(a[2]), "r"(a[3]), "r"(b[0]), "r"(b[1]));
}

// bf16x8 (uint4) -> 8x fma into acc
__device__ __forceinline__ void acc8(float* acc, uint4 v, float c) {
    float2 f0 = __bfloat1622float2(*reinterpret_cast<__nv_bfloat162*>(&v.x));
    float2 f1 = __bfloat1622float2(*reinterpret_cast<__nv_bfloat162*>(&v.y));
    float2 f2 = __bfloat1622float2(*reinterpret_cast<__nv_bfloat162*>(&v.z));
    float2 f3 = __bfloat1622float2(*reinterpret_cast<__nv_bfloat162*>(&v.w));
    acc[0] = fmaf(c, f0.x, acc[0]); acc[1] = fmaf(c, f0.y, acc[1]);
    acc[2] = fmaf(c, f1.x, acc[2]); acc[3] = fmaf(c, f1.y, acc[3]);
    acc[4] = fmaf(c, f2.x, acc[4]); acc[5] = fmaf(c, f2.y, acc[5]);
    acc[6] = fmaf(c, f3.x, acc[6]); acc[7] = fmaf(c, f3.y, acc[7]);
}

// node aggregation core: returns post-ReLU 8-value slice for node d (cols lane*8..lane*8+7)
__device__ __forceinline__ void node_aggregate(int d, int lane, const float* __restrict__ b,
                                               float* r) {
    const int beg = g_off[d];
    const int end = g_off[d + 1];
    const uint4* __restrict__ T = reinterpret_cast<const uint4*>(g_tb);
    const int2*  __restrict__ P = g_epack;

    float acc[8] = {0.f, 0.f, 0.f, 0.f, 0.f, 0.f, 0.f, 0.f};

    int e = beg;
#pragma unroll 1
    for (; e + 4 <= end; e += 4) {
        int2 p0 = __ldg(P + e + 0);
        int2 p1 = __ldg(P + e + 1);
        int2 p2 = __ldg(P + e + 2);
        int2 p3 = __ldg(P + e + 3);
        uint4 v0 = __ldg(T + (size_t)p0.x * 32 + lane);
        uint4 v1 = __ldg(T + (size_t)p1.x * 32 + lane);
        uint4 v2 = __ldg(T + (size_t)p2.x * 32 + lane);
        uint4 v3 = __ldg(T + (size_t)p3.x * 32 + lane);
        acc8(acc, v0, __int_as_float(p0.y));
        acc8(acc, v1, __int_as_float(p1.y));
        acc8(acc, v2, __int_as_float(p2.y));
        acc8(acc, v3, __int_as_float(p3.y));
    }
    for (; e < end; e++) {
        int2 p = __ldg(P + e);
        uint4 v = __ldg(T + (size_t)p.x * 32 + lane);
        acc8(acc, v, __int_as_float(p.y));
    }

    const float dd = g_dinv[d];
    acc8(acc, __ldg(T + (size_t)d * 32 + lane), dd * dd);

    const float4* bp = reinterpret_cast<const float4*>(b) + lane * 2;
    float4 b0 = __ldg(bp);
    float4 b1 = __ldg(bp + 1);
    r[0] = fmaxf(acc[0] + b0.x, 0.0f);
    r[1] = fmaxf(acc[1] + b0.y, 0.0f);
    r[2] = fmaxf(acc[2] + b0.z, 0.0f);
    r[3] = fmaxf(acc[3] + b0.w, 0.0f);
    r[4] = fmaxf(acc[4] + b1.x, 0.0f);
    r[5] = fmaxf(acc[5] + b1.y, 0.0f);
    r[6] = fmaxf(acc[6] + b1.z, 0.0f);
    r[7] = fmaxf(acc[7] + b1.w, 0.0f);
}

// ---------------- fused conversions: xconv + wtrans(W1) + wtrans(W2) + zero gv ----
__global__ void convall_kernel(const float* __restrict__ x,
                               const float* __restrict__ W1,
                               const float* __restrict__ W2, int n)
{
    const int idx = blockIdx.x * 256 + threadIdx.x;
    if (idx < HDIM * 128) {
        int nn = idx >> 7, kk = idx & 127;
        float w = W1[(size_t)kk * HDIM + nn];
        __nv_bfloat16 h = __float2bfloat16_rn(w);
        g_w1t_hi[idx] = h;
        g_w1t_lo[idx] = __float2bfloat16_rn(w - __bfloat162float(h));
    }
    if (idx < HDIM * HDIM) {
        int nn = idx >> 8, kk = idx & 255;
        float w = W2[(size_t)kk * HDIM + nn];
        __nv_bfloat16 h = __float2bfloat16_rn(w);
        g_w2t_hi[idx] = h;
        g_w2t_lo[idx] = __float2bfloat16_rn(w - __bfloat162float(h));
    }
    if (idx < HDIM) g_gv[idx] = 0.0f;
    if (idx < n * 32) {
        float4 v = reinterpret_cast<const float4*>(x)[idx];
        __nv_bfloat162 p0 = __float22bfloat162_rn(make_float2(v.x, v.y));
        __nv_bfloat162 p1 = __float22bfloat162_rn(make_float2(v.z, v.w));
        uint2 u;
        u.x = *reinterpret_cast<uint32_t*>(&p0);
        u.y = *reinterpret_cast<uint32_t*>(&p1);
        reinterpret_cast<uint2*>(g_xb)[idx] = u;
    }
}

// ---------------- CSR-build chain (side stream) ----------------
__global__ void prep_kernel(int n)
{
    int i = blockIdx.x * blockDim.x + threadIdx.x;
    if (i < n) g_degi[i] = 0;
}

__global__ void deg_kernel(const int* __restrict__ dst, int E)
{
    int e = blockIdx.x * blockDim.x + threadIdx.x;
    if (e < E) atomicAdd(&g_degi[dst[e]], 1);
}

__global__ void scan1_kernel(int n)
{
    __shared__ int s[SCAN_B];
    int i = blockIdx.x * SCAN_B + threadIdx.x;
    int deg = (i < n) ? g_degi[i] : 0;
    if (i < n) g_dinv[i] = rsqrtf((float)deg + 1.0f);
    s[threadIdx.x] = deg;
    __syncthreads();
    for (int ofs = SCAN_B / 2; ofs > 0; ofs >>= 1) {
        if (threadIdx.x < ofs) s[threadIdx.x] += s[threadIdx.x + ofs];
        __syncthreads();
    }
    if (threadIdx.x == 0) g_part[blockIdx.x] = s[0];
}

__global__ void scan2_kernel(int nblocks, int n, int E)
{
    __shared__ int a[512], b[512];
    int t = threadIdx.x;
    int v = (t < nblocks) ? g_part[t] : 0;
    a[t] = v;
    __syncthreads();
    int* pin = a; int* pout = b;
    for (int ofs = 1; ofs < 512; ofs <<= 1) {
        pout[t] = (t >= ofs) ? pin[t] + pin[t - ofs] : pin[t];
        __syncthreads();
        int* tmp = pin; pin = pout; pout = tmp;
    }
    g_part[t] = (t == 0) ? 0 : pin[t - 1];
    if (t == 0) g_off[n] = E;
}

__global__ void scan3_kernel(int n)
{
    __shared__ int a[SCAN_B], b[SCAN_B];
    int t = threadIdx.x;
    int i = blockIdx.x * SCAN_B + t;
    int v = (i < n) ? g_degi[i] : 0;
    a[t] = v;
    __syncthreads();
    int* pin = a; int* pout = b;
    for (int ofs = 1; ofs < SCAN_B; ofs <<= 1) {
        pout[t] = (t >= ofs) ? pin[t] + pin[t - ofs] : pin[t];
        __syncthreads();
        int* tmp = pin; pin = pout; pout = tmp;
    }
    if (i < n) {
        int excl = (t == 0) ? 0 : pin[t - 1];
        int off = g_part[blockIdx.x] + excl;
        g_off[i] = off;
        g_cur[i] = off;
    }
}

__global__ void scatter_kernel(const int* __restrict__ src, const int* __restrict__ dst, int E)
{
    int e = blockIdx.x * blockDim.x + threadIdx.x;
    if (e < E) {
        int s = src[e];
        int d = dst[e];
        float coef = __ldg(&g_dinv[s]) * __ldg(&g_dinv[d]);
        int pos = atomicAdd(&g_cur[d], 1);
        g_epack[pos] = make_int2(s, __float_as_int(coef));
    }
}

// ---------------- HMMA GEMM v4: C_bf16[M,256] = A_bf16[M,K] @ W[K,256] ----------------
#define ST_A   0
#define ST_BH  16384
#define ST_BL  49152
#define STAGE  81920
#define SM_TOTAL (2 * STAGE)

__global__ __launch_bounds__(512, 1)
void tgemm_kernel(const __nv_bfloat16* __restrict__ A,
                  const __nv_bfloat16* __restrict__ WHI,
                  const __nv_bfloat16* __restrict__ WLO,
                  __nv_bfloat16* __restrict__ C, int M, int K)
{
    extern __shared__ char smem[];
    const uint32_t sb = smem_u32(smem);
    const int tid = threadIdx.x;
    const int wid = tid >> 5;
    const int lane = tid & 31;
    const int warp_m = wid & 3;
    const int warp_n = wid >> 2;
    const int row0 = blockIdx.x * 128;

    float acc[2][8][4];
#pragma unroll
    for (int mt = 0; mt < 2; mt++)
#pragma unroll
        for (int nt = 0; nt < 8; nt++)
#pragma unroll
            for (int q = 0; q < 4; q++) acc[mt][nt][q] = 0.0f;

    const int lr   = lane & 7;
    const int lsel = lane >> 3;
    const int nch  = K >> 6;

    auto stage_load = [&](int c, int buf) {
        const int k0 = c << 6;
        const uint32_t base = sb + buf * STAGE;
#pragma unroll
        for (int i = 0; i < 2; i++) {
            const int idx = tid + (i << 9);
            const int row = idx >> 3;
            const int u   = idx & 7;
            const int grow = min(row0 + row, M - 1);
            cp16(base + ST_A + SWZ(row * 128 + u * 16),
                 A + (size_t)grow * K + k0 + u * 8);
        }
#pragma unroll
        for (int i = 0; i < 4; i++) {
            const int idx = tid + (i << 9);
            const int nr = idx >> 3;
            const int u  = idx & 7;
            const uint32_t sw = SWZ(nr * 128 + u * 16);
            cp16(base + ST_BH + sw, WHI + (size_t)nr * K + k0 + u * 8);
            cp16(base + ST_BL + sw, WLO + (size_t)nr * K + k0 + u * 8);
        }
        CP_COMMIT();
    };

    stage_load(0, 0);

    for (int c = 0; c < nch; c++) {
        if (c + 1 < nch) {
            stage_load(c + 1, (c + 1) & 1);
            asm volatile("cp.async.wait_group 1;" ::: "memory");
        } else {
            asm volatile("cp.async.wait_group 0;" ::: "memory");
        }
        __syncthreads();

        const uint32_t bufb = sb + (c & 1) * STAGE;
#pragma unroll
        for (int kk = 0; kk < 4; kk++) {
            const int kb = kk * 32 + (lsel & 2) * 8;
            uint32_t ah[8];
#pragma unroll
            for (int mt = 0; mt < 2; mt++) {
                const int arow = warp_m * 32 + mt * 16 + (lsel & 1) * 8 + lr;
                const uint32_t aoff = SWZ(arow * 128 + kb);
                ldsm_x4(bufb + ST_A + aoff, ah[mt*4+0], ah[mt*4+1], ah[mt*4+2], ah[mt*4+3]);
            }
            uint32_t bh[16], bl[16];
#pragma unroll
            for (int p = 0; p < 4; p++) {
                const int brow = warp_n * 64 + p * 16 + (lsel >> 1) * 8 + lr;
                const uint32_t boff = SWZ(brow * 128 + kk * 32 + (lsel & 1) * 16);
                ldsm_x4(bufb + ST_BH + boff, bh[p*4+0], bh[p*4+1], bh[p*4+2], bh[p*4+3]);
                ldsm_x4(bufb + ST_BL + boff, bl[p*4+0], bl[p*4+1], bl[p*4+2], bl[p*4+3]);
            }
#pragma unroll
            for (int mt = 0; mt < 2; mt++) {
#pragma unroll
                for (int nt = 0; nt < 8; nt++) {
                    mma_bf16(acc[mt][nt], &ah[mt*4], &bh[nt*2]);
                    mma_bf16(acc[mt][nt], &ah[mt*4], &bl[nt*2]);
                }
            }
        }
        __syncthreads();
    }

    const int tr = lane >> 2;
    const int tc = (lane & 3) * 2;
#pragma unroll
    for (int mt = 0; mt < 2; mt++) {
#pragma unroll
        for (int nt = 0; nt < 8; nt++) {
            const int col = warp_n * 64 + nt * 8 + tc;
            const int r0 = row0 + warp_m * 32 + mt * 16 + tr;
            if (r0 < M) {
                __nv_bfloat162 v = __float22bfloat162_rn(make_float2(acc[mt][nt][0], acc[mt][nt][1]));
                *reinterpret_cast<__nv_bfloat162*>(C + (size_t)r0 * HDIM + col) = v;
            }
            if (r0 + 8 < M) {
                __nv_bfloat162 v = __float22bfloat162_rn(make_float2(acc[mt][nt][2], acc[mt][nt][3]));
                *reinterpret_cast<__nv_bfloat162*>(C + (size_t)(r0 + 8) * HDIM + col) = v;
            }
        }
    }
}

// ---------------- pull layer-1: writes y (bf16) ----------------
__global__ __launch_bounds__(256)
void pull_kernel(const float* __restrict__ b, int n)
{
    const int wid  = threadIdx.x >> 5;
    const int lane = threadIdx.x & 31;
    const int d    = blockIdx.x * 8 + wid;
    if (d >= n) return;

    float r[8];
    node_aggregate(d, lane, b, r);

    __nv_bfloat162 o0 = __float22bfloat162_rn(make_float2(r[0], r[1]));
    __nv_bfloat162 o1 = __float22bfloat162_rn(make_float2(r[2], r[3]));
    __nv_bfloat162 o2 = __float22bfloat162_rn(make_float2(r[4], r[5]));
    __nv_bfloat162 o3 = __float22bfloat162_rn(make_float2(r[6], r[7]));
    uint4 o;
    o.x = *reinterpret_cast<uint32_t*>(&o0);
    o.y = *reinterpret_cast<uint32_t*>(&o1);
    o.z = *reinterpret_cast<uint32_t*>(&o2);
    o.w = *reinterpret_cast<uint32_t*>(&o3);
    reinterpret_cast<uint4*>(g_yb)[(size_t)d * 32 + lane] = o;
}

// ---------------- pull layer-2 fused with mean-pool (register accumulation) --------
// Each warp grid-strides over nodes, accumulating post-ReLU values for its fixed
// 8 columns in registers. Block reduction: warp-private smem rows + one
// atomicAdd per column per block. No atomics in the node loop.
__global__ __launch_bounds__(256)
void pull_sum_kernel(const float* __restrict__ b, int n, int nblocks)
{
    __shared__ float sacc[8][HDIM];
    const int tid  = threadIdx.x;
    const int wid  = tid >> 5;
    const int lane = tid & 31;

    float sum[8] = {0.f, 0.f, 0.f, 0.f, 0.f, 0.f, 0.f, 0.f};

    for (int d = blockIdx.x * 8 + wid; d < n; d += nblocks * 8) {
        float r[8];
        node_aggregate(d, lane, b, r);
#pragma unroll
        for (int j = 0; j < 8; j++) sum[j] += r[j];
    }

#pragma unroll
    for (int j = 0; j < 8; j++)
        sacc[wid][lane * 8 + j] = sum[j];
    __syncthreads();

    float t = 0.0f;
#pragma unroll
    for (int w = 0; w < 8; w++) t += sacc[w][tid];
    atomicAdd(&g_gv[tid], t);
}

// ---------------- final linear ----------------
__global__ void final_kernel(const float* __restrict__ Wl, const float* __restrict__ bl,
                             float* __restrict__ out, float invN)
{
    __shared__ float s[2];
    if (threadIdx.x < 2) s[threadIdx.x] = 0.0f;
    __syncthreads();
    const int j = threadIdx.x;
    const float gj = g_gv[j] * invN;
    atomicAdd(&s[0], gj * Wl[j * 2 + 0]);
    atomicAdd(&s[1], gj * Wl[j * 2 + 1]);
    __syncthreads();
    if (threadIdx.x < 2) out[threadIdx.x] = s[threadIdx.x] + bl[threadIdx.x];
}

// ---------------- launcher ----------------
extern "C" void kernel_launch(void* const* d_in, const int* in_sizes, int n_in,
                              void* d_out, int out_size)
{
    const float* x  = (const float*)d_in[0];
    const int*   ei = (const int*)  d_in[1];
    const float* W1 = (const float*)d_in[3];
    const float* b1 = (const float*)d_in[4];
    const float* W2 = (const float*)d_in[5];
    const float* b2 = (const float*)d_in[6];
    const float* Wl = (const float*)d_in[7];
    const float* bl = (const float*)d_in[8];
    float* out = (float*)d_out;

    const int n = in_sizes[0] / 128;   // 50000
    const int E = in_sizes[1] / 2;     // 800000

    const int* src = ei;
    const int* dst = ei + E;

    __nv_bfloat16 *tb_ptr, *yb_ptr, *xb_ptr;
    cudaGetSymbolAddress((void**)&tb_ptr, g_tb);
    cudaGetSymbolAddress((void**)&yb_ptr, g_yb);
    cudaGetSymbolAddress((void**)&xb_ptr, g_xb);
    __nv_bfloat16 *w1h, *w1l, *w2h, *w2l;
    cudaGetSymbolAddress((void**)&w1h, g_w1t_hi);
    cudaGetSymbolAddress((void**)&w1l, g_w1t_lo);
    cudaGetSymbolAddress((void**)&w2h, g_w2t_hi);
    cudaGetSymbolAddress((void**)&w2l, g_w2t_lo);

    cudaFuncSetAttribute(tgemm_kernel, cudaFuncAttributeMaxDynamicSharedMemorySize, SM_TOTAL);

    const int nScanBlocks = (n + SCAN_B - 1) / SCAN_B;
    const int gemmBlocks = (n + 127) / 128;   // 391
    const int pullBlocks = (n + 7) / 8;       // 6250

    // ---- fork: CSR build on side stream, conversions + GEMM1 on main ----
    cudaEventRecord(g_side.fork, 0);
    cudaStreamWaitEvent(g_side.s, g_side.fork, 0);

    prep_kernel   <<<(n + 255) / 256, 256, 0, g_side.s>>>(n);
    deg_kernel    <<<(E + 255) / 256, 256, 0, g_side.s>>>(dst, E);
    scan1_kernel  <<<nScanBlocks, SCAN_B, 0, g_side.s>>>(n);
    scan2_kernel  <<<1, 512, 0, g_side.s>>>(nScanBlocks, n, E);
    scan3_kernel  <<<nScanBlocks, SCAN_B, 0, g_side.s>>>(n);
    scatter_kernel<<<(E + 255) / 256, 256, 0, g_side.s>>>(src, dst, E);
    cudaEventRecord(g_side.join, g_side.s);

    // main stream: conversions + GEMM1
    convall_kernel<<<(n * 32 + 255) / 256, 256>>>(x, W1, W2, n);
    tgemm_kernel<<<gemmBlocks, 512, SM_TOTAL>>>(xb_ptr, w1h, w1l, tb_ptr, n, 128);

    // join: pull1 needs CSR
    cudaStreamWaitEvent(0, g_side.join, 0);

    pull_kernel<<<pullBlocks, 256>>>(b1, n);
    tgemm_kernel<<<gemmBlocks, 512, SM_TOTAL>>>(yb_ptr, w2h, w2l, tb_ptr, n, HDIM);
    pull_sum_kernel<<<PS_BLOCKS, 256>>>(b2, n, PS_BLOCKS);

    final_kernel<<<1, HDIM>>>(Wl, bl, out, 1.0f / (float)n);
}

// round 14
// speedup vs baseline: 1.1832x; 1.0166x over previous
#include <cuda_runtime.h>
#include <cuda_bf16.h>
#include <cstddef>
#include <cstdint>

#define NMAX   50000
#define EMAX   800000
#define HDIM   256
#define H4     (HDIM / 4)
#define SCAN_B 256
#define PS_BLOCKS 1184   // pull_sum grid

// ---------------- scratch (device globals) ----------------
__device__ __align__(16) __nv_bfloat16 g_tb[(size_t)NMAX * HDIM];  // GEMM output (bf16 messages)
__device__ __align__(16) __nv_bfloat16 g_yb[(size_t)NMAX * HDIM];  // layer-1 activations (bf16)
__device__ __align__(16) __nv_bfloat16 g_xb[(size_t)NMAX * 128];   // input features (bf16)
__device__ float g_dinv[NMAX];
__device__ int   g_degi[NMAX];
__device__ int   g_off [NMAX + 1];
__device__ int   g_cur [NMAX];
__device__ __align__(8) int2 g_epack[EMAX];   // {src, coef-as-int}
__device__ int   g_part[512];
__device__ float g_gv  [HDIM];
// bf16 split weights, transposed to [n][k]
__device__ __align__(16) __nv_bfloat16 g_w1t_hi[HDIM * 128];
__device__ __align__(16) __nv_bfloat16 g_w1t_lo[HDIM * 128];
__device__ __align__(16) __nv_bfloat16 g_w2t_hi[HDIM * HDIM];
__device__ __align__(16) __nv_bfloat16 g_w2t_lo[HDIM * HDIM];

// ---------------- side stream + events (created once at load; not device allocs) ---
struct SideStream {
    cudaStream_t s;
    cudaEvent_t  fork, join;
    SideStream() {
        cudaStreamCreateWithFlags(&s, cudaStreamNonBlocking);
        cudaEventCreateWithFlags(&fork, cudaEventDisableTiming);
        cudaEventCreateWithFlags(&join, cudaEventDisableTiming);
    }
};
static SideStream g_side;

// ---------------- helpers ----------------
__device__ __forceinline__ uint32_t smem_u32(const void* p) {
    uint32_t a;
    asm("{ .reg .u64 t; cvta.to.shared.u64 t, %1; cvt.u32.u64 %0, t; }" : "=r"(a) : "l"(p));
    return a;
}
#define SWZ(off) ((off) ^ (((off) >> 3) & 0x70))

__device__ __forceinline__ void cp16(uint32_t dst, const void* src) {
    asm volatile("cp.async.cg.shared.global [%0], [%1], 16;" :: "r"(dst), "l"(src));
}
#define CP_COMMIT() asm volatile("cp.async.commit_group;" ::: "memory")

__device__ __forceinline__ void ldsm_x4(uint32_t addr, uint32_t& r0, uint32_t& r1,
                                        uint32_t& r2, uint32_t& r3) {
    asm volatile("ldmatrix.sync.aligned.m8n8.x4.shared.b16 {%0,%1,%2,%3}, [%4];"
                 : "=r"(r0), "=r"(r1), "=r"(r2), "=r"(r3) : "r"(addr));
}

__device__ __forceinline__ void mma_bf16(float* d, const uint32_t* a, const uint32_t* b) {
    asm volatile("mma.sync.aligned.m16n8k16.row.col.f32.bf16.bf16.f32 "
                 "{%0,%1,%2,%3}, {%4,%5,%6,%7}, {%8,%9}, {%0,%1,%2,%3};"
                 : "+f"(d[0]), "+f"(d[1]), "+f"(d[2]), "+f"(d[3])
                 : "r"(a[0]), "r"(a[1]), "r"(a[2]), "r"(a[3]), "r"(b[0]), "r"(b[1]));
}

// bf16x8 (uint4) -> 8x fma into acc
__device__ __forceinline__ void acc8(float* acc, uint4 v, float c) {
    float2 f0 = __bfloat1622float2(*reinterpret_cast<__nv_bfloat162*>(&v.x));
    float2 f1 = __bfloat1622float2(*reinterpret_cast<__nv_bfloat162*>(&v.y));
    float2 f2 = __bfloat1622float2(*reinterpret_cast<__nv_bfloat162*>(&v.z));
    float2 f3 = __bfloat1622float2(*reinterpret_cast<__nv_bfloat162*>(&v.w));
    acc[0] = fmaf(c, f0.x, acc[0]); acc[1] = fmaf(c, f0.y, acc[1]);
    acc[2] = fmaf(c, f1.x, acc[2]); acc[3] = fmaf(c, f1.y, acc[3]);
    acc[4] = fmaf(c, f2.x, acc[4]); acc[5] = fmaf(c, f2.y, acc[5]);
    acc[6] = fmaf(c, f3.x, acc[6]); acc[7] = fmaf(c, f3.y, acc[7]);
}

// node aggregation core: post-ReLU 8-value slice for node d (cols lane*8..lane*8+7)
__device__ __forceinline__ void node_aggregate(int d, int lane, const float* __restrict__ b,
                                               float* r) {
    const int beg = g_off[d];
    const int end = g_off[d + 1];
    const uint4* __restrict__ T = reinterpret_cast<const uint4*>(g_tb);
    const int2*  __restrict__ P = g_epack;

    float acc[8] = {0.f, 0.f, 0.f, 0.f, 0.f, 0.f, 0.f, 0.f};

    int e = beg;
#pragma unroll 1
    for (; e + 4 <= end; e += 4) {
        int2 p0 = __ldg(P + e + 0);
        int2 p1 = __ldg(P + e + 1);
        int2 p2 = __ldg(P + e + 2);
        int2 p3 = __ldg(P + e + 3);
        uint4 v0 = __ldg(T + (size_t)p0.x * 32 + lane);
        uint4 v1 = __ldg(T + (size_t)p1.x * 32 + lane);
        uint4 v2 = __ldg(T + (size_t)p2.x * 32 + lane);
        uint4 v3 = __ldg(T + (size_t)p3.x * 32 + lane);
        acc8(acc, v0, __int_as_float(p0.y));
        acc8(acc, v1, __int_as_float(p1.y));
        acc8(acc, v2, __int_as_float(p2.y));
        acc8(acc, v3, __int_as_float(p3.y));
    }
    for (; e < end; e++) {
        int2 p = __ldg(P + e);
        uint4 v = __ldg(T + (size_t)p.x * 32 + lane);
        acc8(acc, v, __int_as_float(p.y));
    }

    const float dd = g_dinv[d];
    acc8(acc, __ldg(T + (size_t)d * 32 + lane), dd * dd);

    const float4* bp = reinterpret_cast<const float4*>(b) + lane * 2;
    float4 b0 = __ldg(bp);
    float4 b1 = __ldg(bp + 1);
    r[0] = fmaxf(acc[0] + b0.x, 0.0f);
    r[1] = fmaxf(acc[1] + b0.y, 0.0f);
    r[2] = fmaxf(acc[2] + b0.z, 0.0f);
    r[3] = fmaxf(acc[3] + b0.w, 0.0f);
    r[4] = fmaxf(acc[4] + b1.x, 0.0f);
    r[5] = fmaxf(acc[5] + b1.y, 0.0f);
    r[6] = fmaxf(acc[6] + b1.z, 0.0f);
    r[7] = fmaxf(acc[7] + b1.w, 0.0f);
}

// ---------------- fused conversions: xconv + wtrans(W1) + wtrans(W2) + zero gv ----
__global__ void convall_kernel(const float* __restrict__ x,
                               const float* __restrict__ W1,
                               const float* __restrict__ W2, int n)
{
    const int idx = blockIdx.x * 256 + threadIdx.x;
    if (idx < HDIM * 128) {
        int nn = idx >> 7, kk = idx & 127;
        float w = W1[(size_t)kk * HDIM + nn];
        __nv_bfloat16 h = __float2bfloat16_rn(w);
        g_w1t_hi[idx] = h;
        g_w1t_lo[idx] = __float2bfloat16_rn(w - __bfloat162float(h));
    }
    if (idx < HDIM * HDIM) {
        int nn = idx >> 8, kk = idx & 255;
        float w = W2[(size_t)kk * HDIM + nn];
        __nv_bfloat16 h = __float2bfloat16_rn(w);
        g_w2t_hi[idx] = h;
        g_w2t_lo[idx] = __float2bfloat16_rn(w - __bfloat162float(h));
    }
    if (idx < HDIM) g_gv[idx] = 0.0f;
    if (idx < n * 32) {
        float4 v = reinterpret_cast<const float4*>(x)[idx];
        __nv_bfloat162 p0 = __float22bfloat162_rn(make_float2(v.x, v.y));
        __nv_bfloat162 p1 = __float22bfloat162_rn(make_float2(v.z, v.w));
        uint2 u;
        u.x = *reinterpret_cast<uint32_t*>(&p0);
        u.y = *reinterpret_cast<uint32_t*>(&p1);
        reinterpret_cast<uint2*>(g_xb)[idx] = u;
    }
}

// ---------------- CSR-build chain (side stream) ----------------
__global__ void prep_kernel(int n)
{
    int i = blockIdx.x * blockDim.x + threadIdx.x;
    if (i < n) g_degi[i] = 0;
}

__global__ void deg_kernel(const int* __restrict__ dst, int E)
{
    int e = blockIdx.x * blockDim.x + threadIdx.x;
    if (e < E) atomicAdd(&g_degi[dst[e]], 1);
}

__global__ void scan1_kernel(int n)
{
    __shared__ int s[SCAN_B];
    int i = blockIdx.x * SCAN_B + threadIdx.x;
    int deg = (i < n) ? g_degi[i] : 0;
    if (i < n) g_dinv[i] = rsqrtf((float)deg + 1.0f);
    s[threadIdx.x] = deg;
    __syncthreads();
    for (int ofs = SCAN_B / 2; ofs > 0; ofs >>= 1) {
        if (threadIdx.x < ofs) s[threadIdx.x] += s[threadIdx.x + ofs];
        __syncthreads();
    }
    if (threadIdx.x == 0) g_part[blockIdx.x] = s[0];
}

__global__ void scan2_kernel(int nblocks, int n, int E)
{
    __shared__ int a[512], b[512];
    int t = threadIdx.x;
    int v = (t < nblocks) ? g_part[t] : 0;
    a[t] = v;
    __syncthreads();
    int* pin = a; int* pout = b;
    for (int ofs = 1; ofs < 512; ofs <<= 1) {
        pout[t] = (t >= ofs) ? pin[t] + pin[t - ofs] : pin[t];
        __syncthreads();
        int* tmp = pin; pin = pout; pout = tmp;
    }
    g_part[t] = (t == 0) ? 0 : pin[t - 1];
    if (t == 0) g_off[n] = E;
}

__global__ void scan3_kernel(int n)
{
    __shared__ int a[SCAN_B], b[SCAN_B];
    int t = threadIdx.x;
    int i = blockIdx.x * SCAN_B + t;
    int v = (i < n) ? g_degi[i] : 0;
    a[t] = v;
    __syncthreads();
    int* pin = a; int* pout = b;
    for (int ofs = 1; ofs < SCAN_B; ofs <<= 1) {
        pout[t] = (t >= ofs) ? pin[t] + pin[t - ofs] : pin[t];
        __syncthreads();
        int* tmp = pin; pin = pout; pout = tmp;
    }
    if (i < n) {
        int excl = (t == 0) ? 0 : pin[t - 1];
        int off = g_part[blockIdx.x] + excl;
        g_off[i] = off;
        g_cur[i] = off;
    }
}

__global__ void scatter_kernel(const int* __restrict__ src, const int* __restrict__ dst, int E)
{
    int e = blockIdx.x * blockDim.x + threadIdx.x;
    if (e < E) {
        int s = src[e];
        int d = dst[e];
        float coef = __ldg(&g_dinv[s]) * __ldg(&g_dinv[d]);
        int pos = atomicAdd(&g_cur[d], 1);
        g_epack[pos] = make_int2(s, __float_as_int(coef));
    }
}

// ---------------- HMMA GEMM v5: CTA 128x128, 96KB smem -> 2 CTAs/SM ----------------
// C_bf16[M,256] = A_bf16[M,K] @ W[K,256]; 2-pass split C = A*Bhi + A*Blo.
// 256 threads / 8 warps, warp tile 32x64. BK=64, double-buffered cp.async.
#define ST_A   0
#define ST_BH  16384
#define ST_BL  32768
#define STAGE  49152
#define SM_TOTAL (2 * STAGE)   // 96 KB

__global__ __launch_bounds__(256, 2)
void tgemm_kernel(const __nv_bfloat16* __restrict__ A,
                  const __nv_bfloat16* __restrict__ WHI,
                  const __nv_bfloat16* __restrict__ WLO,
                  __nv_bfloat16* __restrict__ C, int M, int K)
{
    extern __shared__ char smem[];
    const uint32_t sb = smem_u32(smem);
    const int tid = threadIdx.x;
    const int wid = tid >> 5;
    const int lane = tid & 31;
    const int warp_m = wid & 3;     // 0..3 -> 32 rows each
    const int warp_n = wid >> 2;    // 0..1 -> 64 cols each
    const int row0 = blockIdx.x * 128;
    const int col0 = blockIdx.y * 128;

    float acc[2][8][4];
#pragma unroll
    for (int mt = 0; mt < 2; mt++)
#pragma unroll
        for (int nt = 0; nt < 8; nt++)
#pragma unroll
            for (int q = 0; q < 4; q++) acc[mt][nt][q] = 0.0f;

    const int lr   = lane & 7;
    const int lsel = lane >> 3;
    const int nch  = K >> 6;

    // stage loader: A 1024 cp16 (4/thread), B hi/lo 1024 cp16 each (4/thread)
    auto stage_load = [&](int c, int buf) {
        const int k0 = c << 6;
        const uint32_t base = sb + buf * STAGE;
#pragma unroll
        for (int i = 0; i < 4; i++) {
            const int idx = tid + (i << 8);
            const int row = idx >> 3;
            const int u   = idx & 7;
            const int grow = min(row0 + row, M - 1);
            cp16(base + ST_A + SWZ(row * 128 + u * 16),
                 A + (size_t)grow * K + k0 + u * 8);
        }
#pragma unroll
        for (int i = 0; i < 4; i++) {
            const int idx = tid + (i << 8);
            const int nr = idx >> 3;
            const int u  = idx & 7;
            const uint32_t sw = SWZ(nr * 128 + u * 16);
            cp16(base + ST_BH + sw, WHI + (size_t)(col0 + nr) * K + k0 + u * 8);
            cp16(base + ST_BL + sw, WLO + (size_t)(col0 + nr) * K + k0 + u * 8);
        }
        CP_COMMIT();
    };

    stage_load(0, 0);

    for (int c = 0; c < nch; c++) {
        if (c + 1 < nch) {
            stage_load(c + 1, (c + 1) & 1);
            asm volatile("cp.async.wait_group 1;" ::: "memory");
        } else {
            asm volatile("cp.async.wait_group 0;" ::: "memory");
        }
        __syncthreads();

        const uint32_t bufb = sb + (c & 1) * STAGE;
#pragma unroll
        for (int kk = 0; kk < 4; kk++) {
            const int kb = kk * 32 + (lsel & 2) * 8;
            uint32_t ah[8];
#pragma unroll
            for (int mt = 0; mt < 2; mt++) {
                const int arow = warp_m * 32 + mt * 16 + (lsel & 1) * 8 + lr;
                const uint32_t aoff = SWZ(arow * 128 + kb);
                ldsm_x4(bufb + ST_A + aoff, ah[mt*4+0], ah[mt*4+1], ah[mt*4+2], ah[mt*4+3]);
            }
            uint32_t bh[16], bl[16];
#pragma unroll
            for (int p = 0; p < 4; p++) {
                const int brow = warp_n * 64 + p * 16 + (lsel >> 1) * 8 + lr;
                const uint32_t boff = SWZ(brow * 128 + kk * 32 + (lsel & 1) * 16);
                ldsm_x4(bufb + ST_BH + boff, bh[p*4+0], bh[p*4+1], bh[p*4+2], bh[p*4+3]);
                ldsm_x4(bufb + ST_BL + boff, bl[p*4+0], bl[p*4+1], bl[p*4+2], bl[p*4+3]);
            }
#pragma unroll
            for (int mt = 0; mt < 2; mt++) {
#pragma unroll
                for (int nt = 0; nt < 8; nt++) {
                    mma_bf16(acc[mt][nt], &ah[mt*4], &bh[nt*2]);
                    mma_bf16(acc[mt][nt], &ah[mt*4], &bl[nt*2]);
                }
            }
        }
        __syncthreads();
    }

    const int tr = lane >> 2;
    const int tc = (lane & 3) * 2;
#pragma unroll
    for (int mt = 0; mt < 2; mt++) {
#pragma unroll
        for (int nt = 0; nt < 8; nt++) {
            const int col = col0 + warp_n * 64 + nt * 8 + tc;
            const int r0 = row0 + warp_m * 32 + mt * 16 + tr;
            if (r0 < M) {
                __nv_bfloat162 v = __float22bfloat162_rn(make_float2(acc[mt][nt][0], acc[mt][nt][1]));
                *reinterpret_cast<__nv_bfloat162*>(C + (size_t)r0 * HDIM + col) = v;
            }
            if (r0 + 8 < M) {
                __nv_bfloat162 v = __float22bfloat162_rn(make_float2(acc[mt][nt][2], acc[mt][nt][3]));
                *reinterpret_cast<__nv_bfloat162*>(C + (size_t)(r0 + 8) * HDIM + col) = v;
            }
        }
    }
}

// ---------------- pull layer-1: writes y (bf16) ----------------
__global__ __launch_bounds__(256)
void pull_kernel(const float* __restrict__ b, int n)
{
    const int wid  = threadIdx.x >> 5;
    const int lane = threadIdx.x & 31;
    const int d    = blockIdx.x * 8 + wid;
    if (d >= n) return;

    float r[8];
    node_aggregate(d, lane, b, r);

    __nv_bfloat162 o0 = __float22bfloat162_rn(make_float2(r[0], r[1]));
    __nv_bfloat162 o1 = __float22bfloat162_rn(make_float2(r[2], r[3]));
    __nv_bfloat162 o2 = __float22bfloat162_rn(make_float2(r[4], r[5]));
    __nv_bfloat162 o3 = __float22bfloat162_rn(make_float2(r[6], r[7]));
    uint4 o;
    o.x = *reinterpret_cast<uint32_t*>(&o0);
    o.y = *reinterpret_cast<uint32_t*>(&o1);
    o.z = *reinterpret_cast<uint32_t*>(&o2);
    o.w = *reinterpret_cast<uint32_t*>(&o3);
    reinterpret_cast<uint4*>(g_yb)[(size_t)d * 32 + lane] = o;
}

// ---------------- pull layer-2 fused with mean-pool (register accumulation) --------
__global__ __launch_bounds__(256)
void pull_sum_kernel(const float* __restrict__ b, int n, int nblocks)
{
    __shared__ float sacc[8][HDIM];
    const int tid  = threadIdx.x;
    const int wid  = tid >> 5;
    const int lane = tid & 31;

    float sum[8] = {0.f, 0.f, 0.f, 0.f, 0.f, 0.f, 0.f, 0.f};

    for (int d = blockIdx.x * 8 + wid; d < n; d += nblocks * 8) {
        float r[8];
        node_aggregate(d, lane, b, r);
#pragma unroll
        for (int j = 0; j < 8; j++) sum[j] += r[j];
    }

#pragma unroll
    for (int j = 0; j < 8; j++)
        sacc[wid][lane * 8 + j] = sum[j];
    __syncthreads();

    float t = 0.0f;
#pragma unroll
    for (int w = 0; w < 8; w++) t += sacc[w][tid];
    atomicAdd(&g_gv[tid], t);
}

// ---------------- final linear ----------------
__global__ void final_kernel(const float* __restrict__ Wl, const float* __restrict__ bl,
                             float* __restrict__ out, float invN)
{
    __shared__ float s[2];
    if (threadIdx.x < 2) s[threadIdx.x] = 0.0f;
    __syncthreads();
    const int j = threadIdx.x;
    const float gj = g_gv[j] * invN;
    atomicAdd(&s[0], gj * Wl[j * 2 + 0]);
    atomicAdd(&s[1], gj * Wl[j * 2 + 1]);
    __syncthreads();
    if (threadIdx.x < 2) out[threadIdx.x] = s[threadIdx.x] + bl[threadIdx.x];
}

// ---------------- launcher ----------------
extern "C" void kernel_launch(void* const* d_in, const int* in_sizes, int n_in,
                              void* d_out, int out_size)
{
    const float* x  = (const float*)d_in[0];
    const int*   ei = (const int*)  d_in[1];
    const float* W1 = (const float*)d_in[3];
    const float* b1 = (const float*)d_in[4];
    const float* W2 = (const float*)d_in[5];
    const float* b2 = (const float*)d_in[6];
    const float* Wl = (const float*)d_in[7];
    const float* bl = (const float*)d_in[8];
    float* out = (float*)d_out;

    const int n = in_sizes[0] / 128;   // 50000
    const int E = in_sizes[1] / 2;     // 800000

    const int* src = ei;
    const int* dst = ei + E;

    __nv_bfloat16 *tb_ptr, *yb_ptr, *xb_ptr;
    cudaGetSymbolAddress((void**)&tb_ptr, g_tb);
    cudaGetSymbolAddress((void**)&yb_ptr, g_yb);
    cudaGetSymbolAddress((void**)&xb_ptr, g_xb);
    __nv_bfloat16 *w1h, *w1l, *w2h, *w2l;
    cudaGetSymbolAddress((void**)&w1h, g_w1t_hi);
    cudaGetSymbolAddress((void**)&w1l, g_w1t_lo);
    cudaGetSymbolAddress((void**)&w2h, g_w2t_hi);
    cudaGetSymbolAddress((void**)&w2l, g_w2t_lo);

    cudaFuncSetAttribute(tgemm_kernel, cudaFuncAttributeMaxDynamicSharedMemorySize, SM_TOTAL);

    const int nScanBlocks = (n + SCAN_B - 1) / SCAN_B;
    dim3 gemmGrid((n + 127) / 128, 2);        // 391 x 2 tiles, 2 CTAs/SM
    const int pullBlocks = (n + 7) / 8;       // 6250

    // ---- fork: CSR build on side stream, conversions + GEMM1 on main ----
    cudaEventRecord(g_side.fork, 0);
    cudaStreamWaitEvent(g_side.s, g_side.fork, 0);

    prep_kernel   <<<(n + 255) / 256, 256, 0, g_side.s>>>(n);
    deg_kernel    <<<(E + 255) / 256, 256, 0, g_side.s>>>(dst, E);
    scan1_kernel  <<<nScanBlocks, SCAN_B, 0, g_side.s>>>(n);
    scan2_kernel  <<<1, 512, 0, g_side.s>>>(nScanBlocks, n, E);
    scan3_kernel  <<<nScanBlocks, SCAN_B, 0, g_side.s>>>(n);
    scatter_kernel<<<(E + 255) / 256, 256, 0, g_side.s>>>(src, dst, E);
    cudaEventRecord(g_side.join, g_side.s);

    // main stream: conversions + GEMM1
    convall_kernel<<<(n * 32 + 255) / 256, 256>>>(x, W1, W2, n);
    tgemm_kernel<<<gemmGrid, 256, STAGE * 2>>>(xb_ptr, w1h, w1l, tb_ptr, n, 128);

    // join: pull1 needs CSR
    cudaStreamWaitEvent(0, g_side.join, 0);

    pull_kernel<<<pullBlocks, 256>>>(b1, n);
    tgemm_kernel<<<gemmGrid, 256, STAGE * 2>>>(yb_ptr, w2h, w2l, tb_ptr, n, HDIM);
    pull_sum_kernel<<<PS_BLOCKS, 256>>>(b2, n, PS_BLOCKS);

    final_kernel<<<1, HDIM>>>(Wl, bl, out, 1.0f / (float)n);
}

// round 15
// speedup vs baseline: 1.2713x; 1.0744x over previous
#include <cuda_runtime.h>
#include <cuda_bf16.h>
#include <cuda_fp16.h>
#include <cstddef>
#include <cstdint>

#define NMAX   50000
#define EMAX   800000
#define HDIM   256
#define H4     (HDIM / 4)
#define SCAN_B 256
#define PS_BLOCKS 1184   // pull_sum grid

// ---------------- scratch (device globals) ----------------
__device__ __align__(16) __nv_bfloat16 g_tb[(size_t)NMAX * HDIM];  // GEMM output (bf16 messages)
__device__ __align__(16) __half g_yh[(size_t)NMAX * HDIM];         // layer-1 activations (fp16)
__device__ __align__(16) __nv_bfloat16 g_xb[(size_t)NMAX * 128];   // input features (bf16)
__device__ float g_dinv[NMAX];
__device__ int   g_degi[NMAX];
__device__ int   g_off [NMAX + 1];
__device__ int   g_cur [NMAX];
__device__ __align__(8) int2 g_epack[EMAX];   // {src, coef-as-int}
__device__ int   g_part[512];
__device__ float g_gv  [HDIM];
// weights, transposed to [n][k]: W1 split bf16 hi/lo; W2 single fp16
__device__ __align__(16) __nv_bfloat16 g_w1t_hi[HDIM * 128];
__device__ __align__(16) __nv_bfloat16 g_w1t_lo[HDIM * 128];
__device__ __align__(16) __half g_w2t_h16[HDIM * HDIM];

// ---------------- side stream + events ----------------
struct SideStream {
    cudaStream_t s;
    cudaEvent_t  fork, join;
    SideStream() {
        cudaStreamCreateWithFlags(&s, cudaStreamNonBlocking);
        cudaEventCreateWithFlags(&fork, cudaEventDisableTiming);
        cudaEventCreateWithFlags(&join, cudaEventDisableTiming);
    }
};
static SideStream g_side;

// ---------------- helpers ----------------
__device__ __forceinline__ uint32_t smem_u32(const void* p) {
    uint32_t a;
    asm("{ .reg .u64 t; cvta.to.shared.u64 t, %1; cvt.u32.u64 %0, t; }" : "=r"(a) : "l"(p));
    return a;
}
#define SWZ(off) ((off) ^ (((off) >> 3) & 0x70))

__device__ __forceinline__ void cp16(uint32_t dst, const void* src) {
    asm volatile("cp.async.cg.shared.global [%0], [%1], 16;" :: "r"(dst), "l"(src));
}
#define CP_COMMIT() asm volatile("cp.async.commit_group;" ::: "memory")

__device__ __forceinline__ void ldsm_x4(uint32_t addr, uint32_t& r0, uint32_t& r1,
                                        uint32_t& r2, uint32_t& r3) {
    asm volatile("ldmatrix.sync.aligned.m8n8.x4.shared.b16 {%0,%1,%2,%3}, [%4];"
                 : "=r"(r0), "=r"(r1), "=r"(r2), "=r"(r3) : "r"(addr));
}

__device__ __forceinline__ void mma_bf16(float* d, const uint32_t* a, const uint32_t* b) {
    asm volatile("mma.sync.aligned.m16n8k16.row.col.f32.bf16.bf16.f32 "
                 "{%0,%1,%2,%3}, {%4,%5,%6,%7}, {%8,%9}, {%0,%1,%2,%3};"
                 : "+f"(d[0]), "+f"(d[1]), "+f"(d[2]), "+f"(d[3])
                 : "r"(a[0]), "r"(a[1]), "r"(a[2]), "r"(a[3]), "r"(b[0]), "r"(b[1]));
}

__device__ __forceinline__ void mma_f16(float* d, const uint32_t* a, const uint32_t* b) {
    asm volatile("mma.sync.aligned.m16n8k16.row.col.f32.f16.f16.f32 "
                 "{%0,%1,%2,%3}, {%4,%5,%6,%7}, {%8,%9}, {%0,%1,%2,%3};"
                 : "+f"(d[0]), "+f"(d[1]), "+f"(d[2]), "+f"(d[3])
                 : "r"(a[0]), "r"(a[1]), "r"(a[2]), "r"(a[3]), "r"(b[0]), "r"(b[1]));
}

// bf16x8 (uint4) -> 8x fma into acc
__device__ __forceinline__ void acc8(float* acc, uint4 v, float c) {
    float2 f0 = __bfloat1622float2(*reinterpret_cast<__nv_bfloat162*>(&v.x));
    float2 f1 = __bfloat1622float2(*reinterpret_cast<__nv_bfloat162*>(&v.y));
    float2 f2 = __bfloat1622float2(*reinterpret_cast<__nv_bfloat162*>(&v.z));
    float2 f3 = __bfloat1622float2(*reinterpret_cast<__nv_bfloat162*>(&v.w));
    acc[0] = fmaf(c, f0.x, acc[0]); acc[1] = fmaf(c, f0.y, acc[1]);
    acc[2] = fmaf(c, f1.x, acc[2]); acc[3] = fmaf(c, f1.y, acc[3]);
    acc[4] = fmaf(c, f2.x, acc[4]); acc[5] = fmaf(c, f2.y, acc[5]);
    acc[6] = fmaf(c, f3.x, acc[6]); acc[7] = fmaf(c, f3.y, acc[7]);
}

// node aggregation core: post-ReLU 8-value slice for node d (cols lane*8..lane*8+7)
__device__ __forceinline__ void node_aggregate(int d, int lane, const float* __restrict__ b,
                                               float* r) {
    const int beg = g_off[d];
    const int end = g_off[d + 1];
    const uint4* __restrict__ T = reinterpret_cast<const uint4*>(g_tb);
    const int2*  __restrict__ P = g_epack;

    float acc[8] = {0.f, 0.f, 0.f, 0.f, 0.f, 0.f, 0.f, 0.f};

    int e = beg;
#pragma unroll 1
    for (; e + 4 <= end; e += 4) {
        int2 p0 = __ldg(P + e + 0);
        int2 p1 = __ldg(P + e + 1);
        int2 p2 = __ldg(P + e + 2);
        int2 p3 = __ldg(P + e + 3);
        uint4 v0 = __ldg(T + (size_t)p0.x * 32 + lane);
        uint4 v1 = __ldg(T + (size_t)p1.x * 32 + lane);
        uint4 v2 = __ldg(T + (size_t)p2.x * 32 + lane);
        uint4 v3 = __ldg(T + (size_t)p3.x * 32 + lane);
        acc8(acc, v0, __int_as_float(p0.y));
        acc8(acc, v1, __int_as_float(p1.y));
        acc8(acc, v2, __int_as_float(p2.y));
        acc8(acc, v3, __int_as_float(p3.y));
    }
    for (; e < end; e++) {
        int2 p = __ldg(P + e);
        uint4 v = __ldg(T + (size_t)p.x * 32 + lane);
        acc8(acc, v, __int_as_float(p.y));
    }

    const float dd = g_dinv[d];
    acc8(acc, __ldg(T + (size_t)d * 32 + lane), dd * dd);

    const float4* bp = reinterpret_cast<const float4*>(b) + lane * 2;
    float4 b0 = __ldg(bp);
    float4 b1 = __ldg(bp + 1);
    r[0] = fmaxf(acc[0] + b0.x, 0.0f);
    r[1] = fmaxf(acc[1] + b0.y, 0.0f);
    r[2] = fmaxf(acc[2] + b0.z, 0.0f);
    r[3] = fmaxf(acc[3] + b0.w, 0.0f);
    r[4] = fmaxf(acc[4] + b1.x, 0.0f);
    r[5] = fmaxf(acc[5] + b1.y, 0.0f);
    r[6] = fmaxf(acc[6] + b1.z, 0.0f);
    r[7] = fmaxf(acc[7] + b1.w, 0.0f);
}

// ---------------- fused conversions ----------------
__global__ void convall_kernel(const float* __restrict__ x,
                               const float* __restrict__ W1,
                               const float* __restrict__ W2, int n)
{
    const int idx = blockIdx.x * 256 + threadIdx.x;
    if (idx < HDIM * 128) {
        int nn = idx >> 7, kk = idx & 127;
        float w = W1[(size_t)kk * HDIM + nn];
        __nv_bfloat16 h = __float2bfloat16_rn(w);
        g_w1t_hi[idx] = h;
        g_w1t_lo[idx] = __float2bfloat16_rn(w - __bfloat162float(h));
    }
    if (idx < HDIM * HDIM) {
        int nn = idx >> 8, kk = idx & 255;
        float w = W2[(size_t)kk * HDIM + nn];
        g_w2t_h16[idx] = __float2half_rn(w);
    }
    if (idx < HDIM) g_gv[idx] = 0.0f;
    if (idx < n * 32) {
        float4 v = reinterpret_cast<const float4*>(x)[idx];
        __nv_bfloat162 p0 = __float22bfloat162_rn(make_float2(v.x, v.y));
        __nv_bfloat162 p1 = __float22bfloat162_rn(make_float2(v.z, v.w));
        uint2 u;
        u.x = *reinterpret_cast<uint32_t*>(&p0);
        u.y = *reinterpret_cast<uint32_t*>(&p1);
        reinterpret_cast<uint2*>(g_xb)[idx] = u;
    }
}

// ---------------- CSR-build chain (side stream) ----------------
__global__ void prep_kernel(int n)
{
    int i = blockIdx.x * blockDim.x + threadIdx.x;
    if (i < n) g_degi[i] = 0;
}

__global__ void deg_kernel(const int* __restrict__ dst, int E)
{
    int e = blockIdx.x * blockDim.x + threadIdx.x;
    if (e < E) atomicAdd(&g_degi[dst[e]], 1);
}

__global__ void scan1_kernel(int n)
{
    __shared__ int s[SCAN_B];
    int i = blockIdx.x * SCAN_B + threadIdx.x;
    int deg = (i < n) ? g_degi[i] : 0;
    if (i < n) g_dinv[i] = rsqrtf((float)deg + 1.0f);
    s[threadIdx.x] = deg;
    __syncthreads();
    for (int ofs = SCAN_B / 2; ofs > 0; ofs >>= 1) {
        if (threadIdx.x < ofs) s[threadIdx.x] += s[threadIdx.x + ofs];
        __syncthreads();
    }
    if (threadIdx.x == 0) g_part[blockIdx.x] = s[0];
}

__global__ void scan2_kernel(int nblocks, int n, int E)
{
    __shared__ int a[512], b[512];
    int t = threadIdx.x;
    int v = (t < nblocks) ? g_part[t] : 0;
    a[t] = v;
    __syncthreads();
    int* pin = a; int* pout = b;
    for (int ofs = 1; ofs < 512; ofs <<= 1) {
        pout[t] = (t >= ofs) ? pin[t] + pin[t - ofs] : pin[t];
        __syncthreads();
        int* tmp = pin; pin = pout; pout = tmp;
    }
    g_part[t] = (t == 0) ? 0 : pin[t - 1];
    if (t == 0) g_off[n] = E;
}

__global__ void scan3_kernel(int n)
{
    __shared__ int a[SCAN_B], b[SCAN_B];
    int t = threadIdx.x;
    int i = blockIdx.x * SCAN_B + t;
    int v = (i < n) ? g_degi[i] : 0;
    a[t] = v;
    __syncthreads();
    int* pin = a; int* pout = b;
    for (int ofs = 1; ofs < SCAN_B; ofs <<= 1) {
        pout[t] = (t >= ofs) ? pin[t] + pin[t - ofs] : pin[t];
        __syncthreads();
        int* tmp = pin; pin = pout; pout = tmp;
    }
    if (i < n) {
        int excl = (t == 0) ? 0 : pin[t - 1];
        int off = g_part[blockIdx.x] + excl;
        g_off[i] = off;
        g_cur[i] = off;
    }
}

__global__ void scatter_kernel(const int* __restrict__ src, const int* __restrict__ dst, int E)
{
    int e = blockIdx.x * blockDim.x + threadIdx.x;
    if (e < E) {
        int s = src[e];
        int d = dst[e];
        float coef = __ldg(&g_dinv[s]) * __ldg(&g_dinv[d]);
        int pos = atomicAdd(&g_cur[d], 1);
        g_epack[pos] = make_int2(s, __float_as_int(coef));
    }
}

// ---------------- GEMM1 (bf16 2-pass): C_bf16[M,256] = A_bf16[M,128] @ W1 ----------
#define ST_A   0
#define ST_BH  16384
#define ST_BL  32768
#define STAGE  49152
#define SM_TOTAL (2 * STAGE)   // 96 KB

__global__ __launch_bounds__(256, 2)
void tgemm_kernel(const __nv_bfloat16* __restrict__ A,
                  const __nv_bfloat16* __restrict__ WHI,
                  const __nv_bfloat16* __restrict__ WLO,
                  __half* __restrict__ C, int M, int K)
{
    extern __shared__ char smem[];
    const uint32_t sb = smem_u32(smem);
    const int tid = threadIdx.x;
    const int wid = tid >> 5;
    const int lane = tid & 31;
    const int warp_m = wid & 3;
    const int warp_n = wid >> 2;
    const int row0 = blockIdx.x * 128;
    const int col0 = blockIdx.y * 128;

    float acc[2][8][4];
#pragma unroll
    for (int mt = 0; mt < 2; mt++)
#pragma unroll
        for (int nt = 0; nt < 8; nt++)
#pragma unroll
            for (int q = 0; q < 4; q++) acc[mt][nt][q] = 0.0f;

    const int lr   = lane & 7;
    const int lsel = lane >> 3;
    const int nch  = K >> 6;

    auto stage_load = [&](int c, int buf) {
        const int k0 = c << 6;
        const uint32_t base = sb + buf * STAGE;
#pragma unroll
        for (int i = 0; i < 4; i++) {
            const int idx = tid + (i << 8);
            const int row = idx >> 3;
            const int u   = idx & 7;
            const int grow = min(row0 + row, M - 1);
            cp16(base + ST_A + SWZ(row * 128 + u * 16),
                 A + (size_t)grow * K + k0 + u * 8);
        }
#pragma unroll
        for (int i = 0; i < 4; i++) {
            const int idx = tid + (i << 8);
            const int nr = idx >> 3;
            const int u  = idx & 7;
            const uint32_t sw = SWZ(nr * 128 + u * 16);
            cp16(base + ST_BH + sw, WHI + (size_t)(col0 + nr) * K + k0 + u * 8);
            cp16(base + ST_BL + sw, WLO + (size_t)(col0 + nr) * K + k0 + u * 8);
        }
        CP_COMMIT();
    };

    stage_load(0, 0);

    for (int c = 0; c < nch; c++) {
        if (c + 1 < nch) {
            stage_load(c + 1, (c + 1) & 1);
            asm volatile("cp.async.wait_group 1;" ::: "memory");
        } else {
            asm volatile("cp.async.wait_group 0;" ::: "memory");
        }
        __syncthreads();

        const uint32_t bufb = sb + (c & 1) * STAGE;
#pragma unroll
        for (int kk = 0; kk < 4; kk++) {
            const int kb = kk * 32 + (lsel & 2) * 8;
            uint32_t ah[8];
#pragma unroll
            for (int mt = 0; mt < 2; mt++) {
                const int arow = warp_m * 32 + mt * 16 + (lsel & 1) * 8 + lr;
                const uint32_t aoff = SWZ(arow * 128 + kb);
                ldsm_x4(bufb + ST_A + aoff, ah[mt*4+0], ah[mt*4+1], ah[mt*4+2], ah[mt*4+3]);
            }
            uint32_t bh[16], bl[16];
#pragma unroll
            for (int p = 0; p < 4; p++) {
                const int brow = warp_n * 64 + p * 16 + (lsel >> 1) * 8 + lr;
                const uint32_t boff = SWZ(brow * 128 + kk * 32 + (lsel & 1) * 16);
                ldsm_x4(bufb + ST_BH + boff, bh[p*4+0], bh[p*4+1], bh[p*4+2], bh[p*4+3]);
                ldsm_x4(bufb + ST_BL + boff, bl[p*4+0], bl[p*4+1], bl[p*4+2], bl[p*4+3]);
            }
#pragma unroll
            for (int mt = 0; mt < 2; mt++) {
#pragma unroll
                for (int nt = 0; nt < 8; nt++) {
                    mma_bf16(acc[mt][nt], &ah[mt*4], &bh[nt*2]);
                    mma_bf16(acc[mt][nt], &ah[mt*4], &bl[nt*2]);
                }
            }
        }
        __syncthreads();
    }

    // NOTE: GEMM1's output here is the *message* buffer (t), consumed by pull1.
    // Epilogue stores bf16 into g_tb via the C pointer... (C is declared __half* for
    // uniformity; layer-1 call passes the bf16 buffer and we convert accordingly below)
    const int tr = lane >> 2;
    const int tc = (lane & 3) * 2;
#pragma unroll
    for (int mt = 0; mt < 2; mt++) {
#pragma unroll
        for (int nt = 0; nt < 8; nt++) {
            const int col = col0 + warp_n * 64 + nt * 8 + tc;
            const int r0 = row0 + warp_m * 32 + mt * 16 + tr;
            if (r0 < M) {
                __nv_bfloat162 v = __float22bfloat162_rn(make_float2(acc[mt][nt][0], acc[mt][nt][1]));
                *reinterpret_cast<__nv_bfloat162*>(
                    reinterpret_cast<__nv_bfloat16*>(C) + (size_t)r0 * HDIM + col) = v;
            }
            if (r0 + 8 < M) {
                __nv_bfloat162 v = __float22bfloat162_rn(make_float2(acc[mt][nt][2], acc[mt][nt][3]));
                *reinterpret_cast<__nv_bfloat162*>(
                    reinterpret_cast<__nv_bfloat16*>(C) + (size_t)(r0 + 8) * HDIM + col) = v;
            }
        }
    }
}

// ---------------- GEMM2 (fp16 single-pass): C_bf16[M,256] = A_f16[M,256] @ W2_f16 ---
#define ST2_A  0
#define ST2_B  16384
#define STAGE2 32768
#define SM2_TOTAL (2 * STAGE2)   // 64 KB

__global__ __launch_bounds__(256, 2)
void tgemm2_kernel(const __half* __restrict__ A,
                   const __half* __restrict__ W,
                   __nv_bfloat16* __restrict__ C, int M, int K)
{
    extern __shared__ char smem[];
    const uint32_t sb = smem_u32(smem);
    const int tid = threadIdx.x;
    const int wid = tid >> 5;
    const int lane = tid & 31;
    const int warp_m = wid & 3;
    const int warp_n = wid >> 2;
    const int row0 = blockIdx.x * 128;
    const int col0 = blockIdx.y * 128;

    float acc[2][8][4];
#pragma unroll
    for (int mt = 0; mt < 2; mt++)
#pragma unroll
        for (int nt = 0; nt < 8; nt++)
#pragma unroll
            for (int q = 0; q < 4; q++) acc[mt][nt][q] = 0.0f;

    const int lr   = lane & 7;
    const int lsel = lane >> 3;
    const int nch  = K >> 6;

    auto stage_load = [&](int c, int buf) {
        const int k0 = c << 6;
        const uint32_t base = sb + buf * STAGE2;
#pragma unroll
        for (int i = 0; i < 4; i++) {
            const int idx = tid + (i << 8);
            const int row = idx >> 3;
            const int u   = idx & 7;
            const int grow = min(row0 + row, M - 1);
            cp16(base + ST2_A + SWZ(row * 128 + u * 16),
                 A + (size_t)grow * K + k0 + u * 8);
        }
#pragma unroll
        for (int i = 0; i < 4; i++) {
            const int idx = tid + (i << 8);
            const int nr = idx >> 3;
            const int u  = idx & 7;
            cp16(base + ST2_B + SWZ(nr * 128 + u * 16),
                 W + (size_t)(col0 + nr) * K + k0 + u * 8);
        }
        CP_COMMIT();
    };

    stage_load(0, 0);

    for (int c = 0; c < nch; c++) {
        if (c + 1 < nch) {
            stage_load(c + 1, (c + 1) & 1);
            asm volatile("cp.async.wait_group 1;" ::: "memory");
        } else {
            asm volatile("cp.async.wait_group 0;" ::: "memory");
        }
        __syncthreads();

        const uint32_t bufb = sb + (c & 1) * STAGE2;
#pragma unroll
        for (int kk = 0; kk < 4; kk++) {
            const int kb = kk * 32 + (lsel & 2) * 8;
            uint32_t ah[8];
#pragma unroll
            for (int mt = 0; mt < 2; mt++) {
                const int arow = warp_m * 32 + mt * 16 + (lsel & 1) * 8 + lr;
                const uint32_t aoff = SWZ(arow * 128 + kb);
                ldsm_x4(bufb + ST2_A + aoff, ah[mt*4+0], ah[mt*4+1], ah[mt*4+2], ah[mt*4+3]);
            }
            uint32_t bh[16];
#pragma unroll
            for (int p = 0; p < 4; p++) {
                const int brow = warp_n * 64 + p * 16 + (lsel >> 1) * 8 + lr;
                const uint32_t boff = SWZ(brow * 128 + kk * 32 + (lsel & 1) * 16);
                ldsm_x4(bufb + ST2_B + boff, bh[p*4+0], bh[p*4+1], bh[p*4+2], bh[p*4+3]);
            }
#pragma unroll
            for (int mt = 0; mt < 2; mt++) {
#pragma unroll
                for (int nt = 0; nt < 8; nt++)
                    mma_f16(acc[mt][nt], &ah[mt*4], &bh[nt*2]);
            }
        }
        __syncthreads();
    }

    const int tr = lane >> 2;
    const int tc = (lane & 3) * 2;
#pragma unroll
    for (int mt = 0; mt < 2; mt++) {
#pragma unroll
        for (int nt = 0; nt < 8; nt++) {
            const int col = col0 + warp_n * 64 + nt * 8 + tc;
            const int r0 = row0 + warp_m * 32 + mt * 16 + tr;
            if (r0 < M) {
                __nv_bfloat162 v = __float22bfloat162_rn(make_float2(acc[mt][nt][0], acc[mt][nt][1]));
                *reinterpret_cast<__nv_bfloat162*>(C + (size_t)r0 * HDIM + col) = v;
            }
            if (r0 + 8 < M) {
                __nv_bfloat162 v = __float22bfloat162_rn(make_float2(acc[mt][nt][2], acc[mt][nt][3]));
                *reinterpret_cast<__nv_bfloat162*>(C + (size_t)(r0 + 8) * HDIM + col) = v;
            }
        }
    }
}

// ---------------- pull layer-1: writes y (fp16) ----------------
__global__ __launch_bounds__(256)
void pull_kernel(const float* __restrict__ b, int n)
{
    const int wid  = threadIdx.x >> 5;
    const int lane = threadIdx.x & 31;
    const int d    = blockIdx.x * 8 + wid;
    if (d >= n) return;

    float r[8];
    node_aggregate(d, lane, b, r);

    __half2 o0 = __float22half2_rn(make_float2(r[0], r[1]));
    __half2 o1 = __float22half2_rn(make_float2(r[2], r[3]));
    __half2 o2 = __float22half2_rn(make_float2(r[4], r[5]));
    __half2 o3 = __float22half2_rn(make_float2(r[6], r[7]));
    uint4 o;
    o.x = *reinterpret_cast<uint32_t*>(&o0);
    o.y = *reinterpret_cast<uint32_t*>(&o1);
    o.z = *reinterpret_cast<uint32_t*>(&o2);
    o.w = *reinterpret_cast<uint32_t*>(&o3);
    reinterpret_cast<uint4*>(g_yh)[(size_t)d * 32 + lane] = o;
}

// ---------------- pull layer-2 fused with mean-pool (register accumulation) --------
__global__ __launch_bounds__(256)
void pull_sum_kernel(const float* __restrict__ b, int n, int nblocks)
{
    __shared__ float sacc[8][HDIM];
    const int tid  = threadIdx.x;
    const int wid  = tid >> 5;
    const int lane = tid & 31;

    float sum[8] = {0.f, 0.f, 0.f, 0.f, 0.f, 0.f, 0.f, 0.f};

    for (int d = blockIdx.x * 8 + wid; d < n; d += nblocks * 8) {
        float r[8];
        node_aggregate(d, lane, b, r);
#pragma unroll
        for (int j = 0; j < 8; j++) sum[j] += r[j];
    }

#pragma unroll
    for (int j = 0; j < 8; j++)
        sacc[wid][lane * 8 + j] = sum[j];
    __syncthreads();

    float t = 0.0f;
#pragma unroll
    for (int w = 0; w < 8; w++) t += sacc[w][tid];
    atomicAdd(&g_gv[tid], t);
}

// ---------------- final linear ----------------
__global__ void final_kernel(const float* __restrict__ Wl, const float* __restrict__ bl,
                             float* __restrict__ out, float invN)
{
    __shared__ float s[2];
    if (threadIdx.x < 2) s[threadIdx.x] = 0.0f;
    __syncthreads();
    const int j = threadIdx.x;
    const float gj = g_gv[j] * invN;
    atomicAdd(&s[0], gj * Wl[j * 2 + 0]);
    atomicAdd(&s[1], gj * Wl[j * 2 + 1]);
    __syncthreads();
    if (threadIdx.x < 2) out[threadIdx.x] = s[threadIdx.x] + bl[threadIdx.x];
}

// ---------------- launcher ----------------
extern "C" void kernel_launch(void* const* d_in, const int* in_sizes, int n_in,
                              void* d_out, int out_size)
{
    const float* x  = (const float*)d_in[0];
    const int*   ei = (const int*)  d_in[1];
    const float* W1 = (const float*)d_in[3];
    const float* b1 = (const float*)d_in[4];
    const float* W2 = (const float*)d_in[5];
    const float* b2 = (const float*)d_in[6];
    const float* Wl = (const float*)d_in[7];
    const float* bl = (const float*)d_in[8];
    float* out = (float*)d_out;

    const int n = in_sizes[0] / 128;   // 50000
    const int E = in_sizes[1] / 2;     // 800000

    const int* src = ei;
    const int* dst = ei + E;

    __nv_bfloat16 *tb_ptr, *xb_ptr;
    __half *yh_ptr, *w2h16;
    cudaGetSymbolAddress((void**)&tb_ptr, g_tb);
    cudaGetSymbolAddress((void**)&yh_ptr, g_yh);
    cudaGetSymbolAddress((void**)&xb_ptr, g_xb);
    cudaGetSymbolAddress((void**)&w2h16, g_w2t_h16);
    __nv_bfloat16 *w1h, *w1l;
    cudaGetSymbolAddress((void**)&w1h, g_w1t_hi);
    cudaGetSymbolAddress((void**)&w1l, g_w1t_lo);

    cudaFuncSetAttribute(tgemm_kernel, cudaFuncAttributeMaxDynamicSharedMemorySize, SM_TOTAL);
    cudaFuncSetAttribute(tgemm2_kernel, cudaFuncAttributeMaxDynamicSharedMemorySize, SM2_TOTAL);

    const int nScanBlocks = (n + SCAN_B - 1) / SCAN_B;
    dim3 gemmGrid((n + 127) / 128, 2);        // 391 x 2 tiles
    const int pullBlocks = (n + 7) / 8;       // 6250

    // ---- fork: CSR build on side stream, conversions + GEMM1 on main ----
    cudaEventRecord(g_side.fork, 0);
    cudaStreamWaitEvent(g_side.s, g_side.fork, 0);

    prep_kernel   <<<(n + 255) / 256, 256, 0, g_side.s>>>(n);
    deg_kernel    <<<(E + 255) / 256, 256, 0, g_side.s>>>(dst, E);
    scan1_kernel  <<<nScanBlocks, SCAN_B, 0, g_side.s>>>(n);
    scan2_kernel  <<<1, 512, 0, g_side.s>>>(nScanBlocks, n, E);
    scan3_kernel  <<<nScanBlocks, SCAN_B, 0, g_side.s>>>(n);
    scatter_kernel<<<(E + 255) / 256, 256, 0, g_side.s>>>(src, dst, E);
    cudaEventRecord(g_side.join, g_side.s);

    // main stream: conversions + GEMM1 (writes bf16 messages into g_tb)
    convall_kernel<<<(n * 32 + 255) / 256, 256>>>(x, W1, W2, n);
    tgemm_kernel<<<gemmGrid, 256, SM_TOTAL>>>(xb_ptr, w1h, w1l,
                                              (__half*)tb_ptr, n, 128);

    // join: pull1 needs CSR
    cudaStreamWaitEvent(0, g_side.join, 0);

    pull_kernel<<<pullBlocks, 256>>>(b1, n);                                  // y fp16
    tgemm2_kernel<<<gemmGrid, 256, SM2_TOTAL>>>(yh_ptr, w2h16, tb_ptr, n, HDIM);
    pull_sum_kernel<<<PS_BLOCKS, 256>>>(b2, n, PS_BLOCKS);

    final_kernel<<<1, HDIM>>>(Wl, bl, out, 1.0f / (float)n);
}

// round 16
// speedup vs baseline: 1.3567x; 1.0672x over previous
#include <cuda_runtime.h>
#include <cuda_bf16.h>
#include <cuda_fp16.h>
#include <cstddef>
#include <cstdint>

#define NMAX   50000
#define EMAX   800000
#define HDIM   256
#define H4     (HDIM / 4)
#define SCAN_B 256
#define PS_BLOCKS 1184   // pull_sum grid

// ---------------- scratch (device globals) ----------------
__device__ __align__(16) __half g_th[(size_t)NMAX * HDIM];   // GEMM output (fp16 messages)
__device__ __align__(16) __half g_yh[(size_t)NMAX * HDIM];   // layer-1 activations (fp16)
__device__ __align__(16) __half g_xh[(size_t)NMAX * 128];    // input features (fp16)
__device__ float g_dinv[NMAX];
__device__ int   g_degi[NMAX];
__device__ int   g_off [NMAX + 1];
__device__ int   g_cur [NMAX];
__device__ __align__(8) int2 g_epack[EMAX];   // {src, coef-as-int}
__device__ int   g_part[512];
__device__ float g_gv  [HDIM];
// fp16 weights, transposed to [n][k]
__device__ __align__(16) __half g_w1t_h16[HDIM * 128];
__device__ __align__(16) __half g_w2t_h16[HDIM * HDIM];

// ---------------- side stream + events ----------------
struct SideStream {
    cudaStream_t s;
    cudaEvent_t  fork, join;
    SideStream() {
        cudaStreamCreateWithFlags(&s, cudaStreamNonBlocking);
        cudaEventCreateWithFlags(&fork, cudaEventDisableTiming);
        cudaEventCreateWithFlags(&join, cudaEventDisableTiming);
    }
};
static SideStream g_side;

// ---------------- helpers ----------------
__device__ __forceinline__ uint32_t smem_u32(const void* p) {
    uint32_t a;
    asm("{ .reg .u64 t; cvta.to.shared.u64 t, %1; cvt.u32.u64 %0, t; }" : "=r"(a) : "l"(p));
    return a;
}
#define SWZ(off) ((off) ^ (((off) >> 3) & 0x70))

__device__ __forceinline__ void cp16(uint32_t dst, const void* src) {
    asm volatile("cp.async.cg.shared.global [%0], [%1], 16;" :: "r"(dst), "l"(src));
}
#define CP_COMMIT() asm volatile("cp.async.commit_group;" ::: "memory")

__device__ __forceinline__ void ldsm_x4(uint32_t addr, uint32_t& r0, uint32_t& r1,
                                        uint32_t& r2, uint32_t& r3) {
    asm volatile("ldmatrix.sync.aligned.m8n8.x4.shared.b16 {%0,%1,%2,%3}, [%4];"
                 : "=r"(r0), "=r"(r1), "=r"(r2), "=r"(r3) : "r"(addr));
}

__device__ __forceinline__ void mma_f16(float* d, const uint32_t* a, const uint32_t* b) {
    asm volatile("mma.sync.aligned.m16n8k16.row.col.f32.f16.f16.f32 "
                 "{%0,%1,%2,%3}, {%4,%5,%6,%7}, {%8,%9}, {%0,%1,%2,%3};"
                 : "+f"(d[0]), "+f"(d[1]), "+f"(d[2]), "+f"(d[3])
                 : "r"(a[0]), "r"(a[1]), "r"(a[2]), "r"(a[3]), "r"(b[0]), "r"(b[1]));
}

// fp16x8 (uint4) -> 8x fma into acc
__device__ __forceinline__ void acc8(float* acc, uint4 v, float c) {
    float2 f0 = __half22float2(*reinterpret_cast<__half2*>(&v.x));
    float2 f1 = __half22float2(*reinterpret_cast<__half2*>(&v.y));
    float2 f2 = __half22float2(*reinterpret_cast<__half2*>(&v.z));
    float2 f3 = __half22float2(*reinterpret_cast<__half2*>(&v.w));
    acc[0] = fmaf(c, f0.x, acc[0]); acc[1] = fmaf(c, f0.y, acc[1]);
    acc[2] = fmaf(c, f1.x, acc[2]); acc[3] = fmaf(c, f1.y, acc[3]);
    acc[4] = fmaf(c, f2.x, acc[4]); acc[5] = fmaf(c, f2.y, acc[5]);
    acc[6] = fmaf(c, f3.x, acc[6]); acc[7] = fmaf(c, f3.y, acc[7]);
}

// node aggregation core: post-ReLU 8-value slice for node d (cols lane*8..lane*8+7)
__device__ __forceinline__ void node_aggregate(int d, int lane, const float* __restrict__ b,
                                               float* r) {
    const int beg = g_off[d];
    const int end = g_off[d + 1];
    const uint4* __restrict__ T = reinterpret_cast<const uint4*>(g_th);
    const int2*  __restrict__ P = g_epack;

    float acc[8] = {0.f, 0.f, 0.f, 0.f, 0.f, 0.f, 0.f, 0.f};

    int e = beg;
#pragma unroll 1
    for (; e + 4 <= end; e += 4) {
        int2 p0 = __ldg(P + e + 0);
        int2 p1 = __ldg(P + e + 1);
        int2 p2 = __ldg(P + e + 2);
        int2 p3 = __ldg(P + e + 3);
        uint4 v0 = __ldg(T + (size_t)p0.x * 32 + lane);
        uint4 v1 = __ldg(T + (size_t)p1.x * 32 + lane);
        uint4 v2 = __ldg(T + (size_t)p2.x * 32 + lane);
        uint4 v3 = __ldg(T + (size_t)p3.x * 32 + lane);
        acc8(acc, v0, __int_as_float(p0.y));
        acc8(acc, v1, __int_as_float(p1.y));
        acc8(acc, v2, __int_as_float(p2.y));
        acc8(acc, v3, __int_as_float(p3.y));
    }
    for (; e < end; e++) {
        int2 p = __ldg(P + e);
        uint4 v = __ldg(T + (size_t)p.x * 32 + lane);
        acc8(acc, v, __int_as_float(p.y));
    }

    const float dd = g_dinv[d];
    acc8(acc, __ldg(T + (size_t)d * 32 + lane), dd * dd);

    const float4* bp = reinterpret_cast<const float4*>(b) + lane * 2;
    float4 b0 = __ldg(bp);
    float4 b1 = __ldg(bp + 1);
    r[0] = fmaxf(acc[0] + b0.x, 0.0f);
    r[1] = fmaxf(acc[1] + b0.y, 0.0f);
    r[2] = fmaxf(acc[2] + b0.z, 0.0f);
    r[3] = fmaxf(acc[3] + b0.w, 0.0f);
    r[4] = fmaxf(acc[4] + b1.x, 0.0f);
    r[5] = fmaxf(acc[5] + b1.y, 0.0f);
    r[6] = fmaxf(acc[6] + b1.z, 0.0f);
    r[7] = fmaxf(acc[7] + b1.w, 0.0f);
}

// ---------------- fused conversions: x->fp16, W1/W2 transpose->fp16, zero gv ------
__global__ void convall_kernel(const float* __restrict__ x,
                               const float* __restrict__ W1,
                               const float* __restrict__ W2, int n)
{
    const int idx = blockIdx.x * 256 + threadIdx.x;
    if (idx < HDIM * 128) {
        int nn = idx >> 7, kk = idx & 127;
        g_w1t_h16[idx] = __float2half_rn(W1[(size_t)kk * HDIM + nn]);
    }
    if (idx < HDIM * HDIM) {
        int nn = idx >> 8, kk = idx & 255;
        g_w2t_h16[idx] = __float2half_rn(W2[(size_t)kk * HDIM + nn]);
    }
    if (idx < HDIM) g_gv[idx] = 0.0f;
    if (idx < n * 32) {
        float4 v = reinterpret_cast<const float4*>(x)[idx];
        __half2 p0 = __float22half2_rn(make_float2(v.x, v.y));
        __half2 p1 = __float22half2_rn(make_float2(v.z, v.w));
        uint2 u;
        u.x = *reinterpret_cast<uint32_t*>(&p0);
        u.y = *reinterpret_cast<uint32_t*>(&p1);
        reinterpret_cast<uint2*>(g_xh)[idx] = u;
    }
}

// ---------------- CSR-build chain (side stream) ----------------
__global__ void prep_kernel(int n)
{
    int i = blockIdx.x * blockDim.x + threadIdx.x;
    if (i < n) g_degi[i] = 0;
}

__global__ void deg_kernel(const int* __restrict__ dst, int E)
{
    int e = blockIdx.x * blockDim.x + threadIdx.x;
    if (e < E) atomicAdd(&g_degi[dst[e]], 1);
}

__global__ void scan1_kernel(int n)
{
    __shared__ int s[SCAN_B];
    int i = blockIdx.x * SCAN_B + threadIdx.x;
    int deg = (i < n) ? g_degi[i] : 0;
    if (i < n) g_dinv[i] = rsqrtf((float)deg + 1.0f);
    s[threadIdx.x] = deg;
    __syncthreads();
    for (int ofs = SCAN_B / 2; ofs > 0; ofs >>= 1) {
        if (threadIdx.x < ofs) s[threadIdx.x] += s[threadIdx.x + ofs];
        __syncthreads();
    }
    if (threadIdx.x == 0) g_part[blockIdx.x] = s[0];
}

__global__ void scan2_kernel(int nblocks, int n, int E)
{
    __shared__ int a[512], b[512];
    int t = threadIdx.x;
    int v = (t < nblocks) ? g_part[t] : 0;
    a[t] = v;
    __syncthreads();
    int* pin = a; int* pout = b;
    for (int ofs = 1; ofs < 512; ofs <<= 1) {
        pout[t] = (t >= ofs) ? pin[t] + pin[t - ofs] : pin[t];
        __syncthreads();
        int* tmp = pin; pin = pout; pout = tmp;
    }
    g_part[t] = (t == 0) ? 0 : pin[t - 1];
    if (t == 0) g_off[n] = E;
}

__global__ void scan3_kernel(int n)
{
    __shared__ int a[SCAN_B], b[SCAN_B];
    int t = threadIdx.x;
    int i = blockIdx.x * SCAN_B + t;
    int v = (i < n) ? g_degi[i] : 0;
    a[t] = v;
    __syncthreads();
    int* pin = a; int* pout = b;
    for (int ofs = 1; ofs < SCAN_B; ofs <<= 1) {
        pout[t] = (t >= ofs) ? pin[t] + pin[t - ofs] : pin[t];
        __syncthreads();
        int* tmp = pin; pin = pout; pout = tmp;
    }
    if (i < n) {
        int excl = (t == 0) ? 0 : pin[t - 1];
        int off = g_part[blockIdx.x] + excl;
        g_off[i] = off;
        g_cur[i] = off;
    }
}

__global__ void scatter_kernel(const int* __restrict__ src, const int* __restrict__ dst, int E)
{
    int e = blockIdx.x * blockDim.x + threadIdx.x;
    if (e < E) {
        int s = src[e];
        int d = dst[e];
        float coef = __ldg(&g_dinv[s]) * __ldg(&g_dinv[d]);
        int pos = atomicAdd(&g_cur[d], 1);
        g_epack[pos] = make_int2(s, __float_as_int(coef));
    }
}

// ---------------- fp16 GEMM (both layers): C_f16[M,256] = A_f16[M,K] @ W_f16[K,256] -
// CTA 128x128, 256 threads / 8 warps, warp tile 32x64, BK=64, double-buffered cp.async.
#define ST_A   0
#define ST_B   16384
#define STAGE  32768
#define SM_TOTAL (2 * STAGE)   // 64 KB

__global__ __launch_bounds__(256, 2)
void tgemm_kernel(const __half* __restrict__ A,
                  const __half* __restrict__ W,
                  __half* __restrict__ C, int M, int K)
{
    extern __shared__ char smem[];
    const uint32_t sb = smem_u32(smem);
    const int tid = threadIdx.x;
    const int wid = tid >> 5;
    const int lane = tid & 31;
    const int warp_m = wid & 3;
    const int warp_n = wid >> 2;
    const int row0 = blockIdx.x * 128;
    const int col0 = blockIdx.y * 128;

    float acc[2][8][4];
#pragma unroll
    for (int mt = 0; mt < 2; mt++)
#pragma unroll
        for (int nt = 0; nt < 8; nt++)
#pragma unroll
            for (int q = 0; q < 4; q++) acc[mt][nt][q] = 0.0f;

    const int lr   = lane & 7;
    const int lsel = lane >> 3;
    const int nch  = K >> 6;

    auto stage_load = [&](int c, int buf) {
        const int k0 = c << 6;
        const uint32_t base = sb + buf * STAGE;
#pragma unroll
        for (int i = 0; i < 4; i++) {
            const int idx = tid + (i << 8);
            const int row = idx >> 3;
            const int u   = idx & 7;
            const int grow = min(row0 + row, M - 1);
            cp16(base + ST_A + SWZ(row * 128 + u * 16),
                 A + (size_t)grow * K + k0 + u * 8);
        }
#pragma unroll
        for (int i = 0; i < 4; i++) {
            const int idx = tid + (i << 8);
            const int nr = idx >> 3;
            const int u  = idx & 7;
            cp16(base + ST_B + SWZ(nr * 128 + u * 16),
                 W + (size_t)(col0 + nr) * K + k0 + u * 8);
        }
        CP_COMMIT();
    };

    stage_load(0, 0);

    for (int c = 0; c < nch; c++) {
        if (c + 1 < nch) {
            stage_load(c + 1, (c + 1) & 1);
            asm volatile("cp.async.wait_group 1;" ::: "memory");
        } else {
            asm volatile("cp.async.wait_group 0;" ::: "memory");
        }
        __syncthreads();

        const uint32_t bufb = sb + (c & 1) * STAGE;
#pragma unroll
        for (int kk = 0; kk < 4; kk++) {
            const int kb = kk * 32 + (lsel & 2) * 8;
            uint32_t ah[8];
#pragma unroll
            for (int mt = 0; mt < 2; mt++) {
                const int arow = warp_m * 32 + mt * 16 + (lsel & 1) * 8 + lr;
                const uint32_t aoff = SWZ(arow * 128 + kb);
                ldsm_x4(bufb + ST_A + aoff, ah[mt*4+0], ah[mt*4+1], ah[mt*4+2], ah[mt*4+3]);
            }
            uint32_t bh[16];
#pragma unroll
            for (int p = 0; p < 4; p++) {
                const int brow = warp_n * 64 + p * 16 + (lsel >> 1) * 8 + lr;
                const uint32_t boff = SWZ(brow * 128 + kk * 32 + (lsel & 1) * 16);
                ldsm_x4(bufb + ST_B + boff, bh[p*4+0], bh[p*4+1], bh[p*4+2], bh[p*4+3]);
            }
#pragma unroll
            for (int mt = 0; mt < 2; mt++) {
#pragma unroll
                for (int nt = 0; nt < 8; nt++)
                    mma_f16(acc[mt][nt], &ah[mt*4], &bh[nt*2]);
            }
        }
        __syncthreads();
    }

    const int tr = lane >> 2;
    const int tc = (lane & 3) * 2;
#pragma unroll
    for (int mt = 0; mt < 2; mt++) {
#pragma unroll
        for (int nt = 0; nt < 8; nt++) {
            const int col = col0 + warp_n * 64 + nt * 8 + tc;
            const int r0 = row0 + warp_m * 32 + mt * 16 + tr;
            if (r0 < M) {
                __half2 v = __float22half2_rn(make_float2(acc[mt][nt][0], acc[mt][nt][1]));
                *reinterpret_cast<__half2*>(C + (size_t)r0 * HDIM + col) = v;
            }
            if (r0 + 8 < M) {
                __half2 v = __float22half2_rn(make_float2(acc[mt][nt][2], acc[mt][nt][3]));
                *reinterpret_cast<__half2*>(C + (size_t)(r0 + 8) * HDIM + col) = v;
            }
        }
    }
}

// ---------------- pull layer-1: writes y (fp16) ----------------
__global__ __launch_bounds__(256)
void pull_kernel(const float* __restrict__ b, int n)
{
    const int wid  = threadIdx.x >> 5;
    const int lane = threadIdx.x & 31;
    const int d    = blockIdx.x * 8 + wid;
    if (d >= n) return;

    float r[8];
    node_aggregate(d, lane, b, r);

    __half2 o0 = __float22half2_rn(make_float2(r[0], r[1]));
    __half2 o1 = __float22half2_rn(make_float2(r[2], r[3]));
    __half2 o2 = __float22half2_rn(make_float2(r[4], r[5]));
    __half2 o3 = __float22half2_rn(make_float2(r[6], r[7]));
    uint4 o;
    o.x = *reinterpret_cast<uint32_t*>(&o0);
    o.y = *reinterpret_cast<uint32_t*>(&o1);
    o.z = *reinterpret_cast<uint32_t*>(&o2);
    o.w = *reinterpret_cast<uint32_t*>(&o3);
    reinterpret_cast<uint4*>(g_yh)[(size_t)d * 32 + lane] = o;
}

// ---------------- pull layer-2 fused with mean-pool (register accumulation) --------
__global__ __launch_bounds__(256)
void pull_sum_kernel(const float* __restrict__ b, int n, int nblocks)
{
    __shared__ float sacc[8][HDIM];
    const int tid  = threadIdx.x;
    const int wid  = tid >> 5;
    const int lane = tid & 31;

    float sum[8] = {0.f, 0.f, 0.f, 0.f, 0.f, 0.f, 0.f, 0.f};

    for (int d = blockIdx.x * 8 + wid; d < n; d += nblocks * 8) {
        float r[8];
        node_aggregate(d, lane, b, r);
#pragma unroll
        for (int j = 0; j < 8; j++) sum[j] += r[j];
    }

#pragma unroll
    for (int j = 0; j < 8; j++)
        sacc[wid][lane * 8 + j] = sum[j];
    __syncthreads();

    float t = 0.0f;
#pragma unroll
    for (int w = 0; w < 8; w++) t += sacc[w][tid];
    atomicAdd(&g_gv[tid], t);
}

// ---------------- final linear ----------------
__global__ void final_kernel(const float* __restrict__ Wl, const float* __restrict__ bl,
                             float* __restrict__ out, float invN)
{
    __shared__ float s[2];
    if (threadIdx.x < 2) s[threadIdx.x] = 0.0f;
    __syncthreads();
    const int j = threadIdx.x;
    const float gj = g_gv[j] * invN;
    atomicAdd(&s[0], gj * Wl[j * 2 + 0]);
    atomicAdd(&s[1], gj * Wl[j * 2 + 1]);
    __syncthreads();
    if (threadIdx.x < 2) out[threadIdx.x] = s[threadIdx.x] + bl[threadIdx.x];
}

// ---------------- launcher ----------------
extern "C" void kernel_launch(void* const* d_in, const int* in_sizes, int n_in,
                              void* d_out, int out_size)
{
    const float* x  = (const float*)d_in[0];
    const int*   ei = (const int*)  d_in[1];
    const float* W1 = (const float*)d_in[3];
    const float* b1 = (const float*)d_in[4];
    const float* W2 = (const float*)d_in[5];
    const float* b2 = (const float*)d_in[6];
    const float* Wl = (const float*)d_in[7];
    const float* bl = (const float*)d_in[8];
    float* out = (float*)d_out;

    const int n = in_sizes[0] / 128;   // 50000
    const int E = in_sizes[1] / 2;     // 800000

    const int* src = ei;
    const int* dst = ei + E;

    __half *th_ptr, *yh_ptr, *xh_ptr, *w1h16, *w2h16;
    cudaGetSymbolAddress((void**)&th_ptr, g_th);
    cudaGetSymbolAddress((void**)&yh_ptr, g_yh);
    cudaGetSymbolAddress((void**)&xh_ptr, g_xh);
    cudaGetSymbolAddress((void**)&w1h16, g_w1t_h16);
    cudaGetSymbolAddress((void**)&w2h16, g_w2t_h16);

    cudaFuncSetAttribute(tgemm_kernel, cudaFuncAttributeMaxDynamicSharedMemorySize, SM_TOTAL);

    const int nScanBlocks = (n + SCAN_B - 1) / SCAN_B;
    dim3 gemmGrid((n + 127) / 128, 2);        // 391 x 2 tiles
    const int pullBlocks = (n + 7) / 8;       // 6250

    // ---- fork: CSR build on side stream, conversions + GEMM1 on main ----
    cudaEventRecord(g_side.fork, 0);
    cudaStreamWaitEvent(g_side.s, g_side.fork, 0);

    prep_kernel   <<<(n + 255) / 256, 256, 0, g_side.s>>>(n);
    deg_kernel    <<<(E + 255) / 256, 256, 0, g_side.s>>>(dst, E);
    scan1_kernel  <<<nScanBlocks, SCAN_B, 0, g_side.s>>>(n);
    scan2_kernel  <<<1, 512, 0, g_side.s>>>(nScanBlocks, n, E);
    scan3_kernel  <<<nScanBlocks, SCAN_B, 0, g_side.s>>>(n);
    scatter_kernel<<<(E + 255) / 256, 256, 0, g_side.s>>>(src, dst, E);
    cudaEventRecord(g_side.join, g_side.s);

    // main stream: conversions + GEMM1
    convall_kernel<<<(n * 32 + 255) / 256, 256>>>(x, W1, W2, n);
    tgemm_kernel<<<gemmGrid, 256, SM_TOTAL>>>(xh_ptr, w1h16, th_ptr, n, 128);

    // join: pull1 needs CSR
    cudaStreamWaitEvent(0, g_side.join, 0);

    pull_kernel<<<pullBlocks, 256>>>(b1, n);
    tgemm_kernel<<<gemmGrid, 256, SM_TOTAL>>>(yh_ptr, w2h16, th_ptr, n, HDIM);
    pull_sum_kernel<<<PS_BLOCKS, 256>>>(b2, n, PS_BLOCKS);

    final_kernel<<<1, HDIM>>>(Wl, bl, out, 1.0f / (float)n);
}

// round 17
// speedup vs baseline: 1.3797x; 1.0170x over previous
#include <cuda_runtime.h>
#include <cuda_bf16.h>
#include <cuda_fp16.h>
#include <cstddef>
#include <cstdint>

#define NMAX   50000
#define EMAX   800000
#define HDIM   256
#define SCAN_B 256
#define PS_BLOCKS 1184

// ---------------- scratch (device globals) ----------------
__device__ __align__(16) __half g_th[(size_t)NMAX * HDIM];   // layer-2 messages (fp16)
__device__ __align__(16) __half g_yh[(size_t)NMAX * HDIM];   // layer-1 activations (fp16)
__device__ __align__(16) __half g_xh[(size_t)NMAX * 128];    // input features (fp16)
__device__ __align__(16) __half g_a1[(size_t)NMAX * 128];    // layer-1 aggregate (fp16)
__device__ float g_dinv[NMAX];
__device__ int   g_degi[NMAX];
__device__ int   g_off [NMAX + 1];
__device__ int   g_cur [NMAX];
__device__ __align__(8) int2 g_epack[EMAX];   // {src, coef-as-int}
__device__ int   g_part[512];
__device__ float g_gv  [HDIM];
// fp16 weights, transposed to [n][k]
__device__ __align__(16) __half g_w1t_h16[HDIM * 128];
__device__ __align__(16) __half g_w2t_h16[HDIM * HDIM];

// ---------------- side stream + events ----------------
struct SideStream {
    cudaStream_t s;
    cudaEvent_t  fork, join;
    SideStream() {
        cudaStreamCreateWithFlags(&s, cudaStreamNonBlocking);
        cudaEventCreateWithFlags(&fork, cudaEventDisableTiming);
        cudaEventCreateWithFlags(&join, cudaEventDisableTiming);
    }
};
static SideStream g_side;

// ---------------- helpers ----------------
__device__ __forceinline__ uint32_t smem_u32(const void* p) {
    uint32_t a;
    asm("{ .reg .u64 t; cvta.to.shared.u64 t, %1; cvt.u32.u64 %0, t; }" : "=r"(a) : "l"(p));
    return a;
}
#define SWZ(off) ((off) ^ (((off) >> 3) & 0x70))

__device__ __forceinline__ void cp16(uint32_t dst, const void* src) {
    asm volatile("cp.async.cg.shared.global [%0], [%1], 16;" :: "r"(dst), "l"(src));
}
#define CP_COMMIT() asm volatile("cp.async.commit_group;" ::: "memory")

__device__ __forceinline__ void ldsm_x4(uint32_t addr, uint32_t& r0, uint32_t& r1,
                                        uint32_t& r2, uint32_t& r3) {
    asm volatile("ldmatrix.sync.aligned.m8n8.x4.shared.b16 {%0,%1,%2,%3}, [%4];"
                 : "=r"(r0), "=r"(r1), "=r"(r2), "=r"(r3) : "r"(addr));
}

__device__ __forceinline__ void mma_f16(float* d, const uint32_t* a, const uint32_t* b) {
    asm volatile("mma.sync.aligned.m16n8k16.row.col.f32.f16.f16.f32 "
                 "{%0,%1,%2,%3}, {%4,%5,%6,%7}, {%8,%9}, {%0,%1,%2,%3};"
                 : "+f"(d[0]), "+f"(d[1]), "+f"(d[2]), "+f"(d[3])
                 : "r"(a[0]), "r"(a[1]), "r"(a[2]), "r"(a[3]), "r"(b[0]), "r"(b[1]));
}

// fp16x8 (uint4) -> 8x fma
__device__ __forceinline__ void acc8(float* acc, uint4 v, float c) {
    float2 f0 = __half22float2(*reinterpret_cast<__half2*>(&v.x));
    float2 f1 = __half22float2(*reinterpret_cast<__half2*>(&v.y));
    float2 f2 = __half22float2(*reinterpret_cast<__half2*>(&v.z));
    float2 f3 = __half22float2(*reinterpret_cast<__half2*>(&v.w));
    acc[0] = fmaf(c, f0.x, acc[0]); acc[1] = fmaf(c, f0.y, acc[1]);
    acc[2] = fmaf(c, f1.x, acc[2]); acc[3] = fmaf(c, f1.y, acc[3]);
    acc[4] = fmaf(c, f2.x, acc[4]); acc[5] = fmaf(c, f2.y, acc[5]);
    acc[6] = fmaf(c, f3.x, acc[6]); acc[7] = fmaf(c, f3.y, acc[7]);
}

// fp16x4 (uint2) -> 4x fma
__device__ __forceinline__ void acc4(float* acc, uint2 v, float c) {
    float2 f0 = __half22float2(*reinterpret_cast<__half2*>(&v.x));
    float2 f1 = __half22float2(*reinterpret_cast<__half2*>(&v.y));
    acc[0] = fmaf(c, f0.x, acc[0]); acc[1] = fmaf(c, f0.y, acc[1]);
    acc[2] = fmaf(c, f1.x, acc[2]); acc[3] = fmaf(c, f1.y, acc[3]);
}

// 256-wide node aggregation (for layer 2 pull_sum): post-ReLU slice
__device__ __forceinline__ void node_aggregate(int d, int lane, const float* __restrict__ b,
                                               float* r) {
    const int beg = g_off[d];
    const int end = g_off[d + 1];
    const uint4* __restrict__ T = reinterpret_cast<const uint4*>(g_th);
    const int2*  __restrict__ P = g_epack;

    float acc[8] = {0.f, 0.f, 0.f, 0.f, 0.f, 0.f, 0.f, 0.f};

    int e = beg;
#pragma unroll 1
    for (; e + 4 <= end; e += 4) {
        int2 p0 = __ldg(P + e + 0);
        int2 p1 = __ldg(P + e + 1);
        int2 p2 = __ldg(P + e + 2);
        int2 p3 = __ldg(P + e + 3);
        uint4 v0 = __ldg(T + (size_t)p0.x * 32 + lane);
        uint4 v1 = __ldg(T + (size_t)p1.x * 32 + lane);
        uint4 v2 = __ldg(T + (size_t)p2.x * 32 + lane);
        uint4 v3 = __ldg(T + (size_t)p3.x * 32 + lane);
        acc8(acc, v0, __int_as_float(p0.y));
        acc8(acc, v1, __int_as_float(p1.y));
        acc8(acc, v2, __int_as_float(p2.y));
        acc8(acc, v3, __int_as_float(p3.y));
    }
    for (; e < end; e++) {
        int2 p = __ldg(P + e);
        uint4 v = __ldg(T + (size_t)p.x * 32 + lane);
        acc8(acc, v, __int_as_float(p.y));
    }

    const float dd = g_dinv[d];
    acc8(acc, __ldg(T + (size_t)d * 32 + lane), dd * dd);

    const float4* bp = reinterpret_cast<const float4*>(b) + lane * 2;
    float4 b0 = __ldg(bp);
    float4 b1 = __ldg(bp + 1);
    r[0] = fmaxf(acc[0] + b0.x, 0.0f);
    r[1] = fmaxf(acc[1] + b0.y, 0.0f);
    r[2] = fmaxf(acc[2] + b0.z, 0.0f);
    r[3] = fmaxf(acc[3] + b0.w, 0.0f);
    r[4] = fmaxf(acc[4] + b1.x, 0.0f);
    r[5] = fmaxf(acc[5] + b1.y, 0.0f);
    r[6] = fmaxf(acc[6] + b1.z, 0.0f);
    r[7] = fmaxf(acc[7] + b1.w, 0.0f);
}

// ---------------- fused conversions ----------------
__global__ void convall_kernel(const float* __restrict__ x,
                               const float* __restrict__ W1,
                               const float* __restrict__ W2, int n)
{
    const int idx = blockIdx.x * 256 + threadIdx.x;
    if (idx < HDIM * 128) {
        int nn = idx >> 7, kk = idx & 127;
        g_w1t_h16[idx] = __float2half_rn(W1[(size_t)kk * HDIM + nn]);
    }
    if (idx < HDIM * HDIM) {
        int nn = idx >> 8, kk = idx & 255;
        g_w2t_h16[idx] = __float2half_rn(W2[(size_t)kk * HDIM + nn]);
    }
    if (idx < HDIM) g_gv[idx] = 0.0f;
    if (idx < n * 32) {
        float4 v = reinterpret_cast<const float4*>(x)[idx];
        __half2 p0 = __float22half2_rn(make_float2(v.x, v.y));
        __half2 p1 = __float22half2_rn(make_float2(v.z, v.w));
        uint2 u;
        u.x = *reinterpret_cast<uint32_t*>(&p0);
        u.y = *reinterpret_cast<uint32_t*>(&p1);
        reinterpret_cast<uint2*>(g_xh)[idx] = u;
    }
}

// ---------------- CSR-build chain (side stream) ----------------
__global__ void prep_kernel(int n)
{
    int i = blockIdx.x * blockDim.x + threadIdx.x;
    if (i < n) g_degi[i] = 0;
}

__global__ void deg_kernel(const int* __restrict__ dst, int E)
{
    int e = blockIdx.x * blockDim.x + threadIdx.x;
    if (e < E) atomicAdd(&g_degi[dst[e]], 1);
}

__global__ void scan1_kernel(int n)
{
    __shared__ int s[SCAN_B];
    int i = blockIdx.x * SCAN_B + threadIdx.x;
    int deg = (i < n) ? g_degi[i] : 0;
    if (i < n) g_dinv[i] = rsqrtf((float)deg + 1.0f);
    s[threadIdx.x] = deg;
    __syncthreads();
    for (int ofs = SCAN_B / 2; ofs > 0; ofs >>= 1) {
        if (threadIdx.x < ofs) s[threadIdx.x] += s[threadIdx.x + ofs];
        __syncthreads();
    }
    if (threadIdx.x == 0) g_part[blockIdx.x] = s[0];
}

__global__ void scan2_kernel(int nblocks, int n, int E)
{
    __shared__ int a[512], b[512];
    int t = threadIdx.x;
    int v = (t < nblocks) ? g_part[t] : 0;
    a[t] = v;
    __syncthreads();
    int* pin = a; int* pout = b;
    for (int ofs = 1; ofs < 512; ofs <<= 1) {
        pout[t] = (t >= ofs) ? pin[t] + pin[t - ofs] : pin[t];
        __syncthreads();
        int* tmp = pin; pin = pout; pout = tmp;
    }
    g_part[t] = (t == 0) ? 0 : pin[t - 1];
    if (t == 0) g_off[n] = E;
}

__global__ void scan3_kernel(int n)
{
    __shared__ int a[SCAN_B], b[SCAN_B];
    int t = threadIdx.x;
    int i = blockIdx.x * SCAN_B + t;
    int v = (i < n) ? g_degi[i] : 0;
    a[t] = v;
    __syncthreads();
    int* pin = a; int* pout = b;
    for (int ofs = 1; ofs < SCAN_B; ofs <<= 1) {
        pout[t] = (t >= ofs) ? pin[t] + pin[t - ofs] : pin[t];
        __syncthreads();
        int* tmp = pin; pin = pout; pout = tmp;
    }
    if (i < n) {
        int excl = (t == 0) ? 0 : pin[t - 1];
        int off = g_part[blockIdx.x] + excl;
        g_off[i] = off;
        g_cur[i] = off;
    }
}

__global__ void scatter_kernel(const int* __restrict__ src, const int* __restrict__ dst, int E)
{
    int e = blockIdx.x * blockDim.x + threadIdx.x;
    if (e < E) {
        int s = src[e];
        int d = dst[e];
        float coef = __ldg(&g_dinv[s]) * __ldg(&g_dinv[d]);
        int pos = atomicAdd(&g_cur[d], 1);
        g_epack[pos] = make_int2(s, __float_as_int(coef));
    }
}

// ---------------- pull1': agg1[d] = Â x  (128-wide gather, fp16) ----------------
__global__ __launch_bounds__(256)
void pull1_kernel(int n)
{
    const int wid  = threadIdx.x >> 5;
    const int lane = threadIdx.x & 31;
    const int d    = blockIdx.x * 8 + wid;
    if (d >= n) return;

    const int beg = g_off[d];
    const int end = g_off[d + 1];
    const uint2* __restrict__ T = reinterpret_cast<const uint2*>(g_xh);  // 32 uint2 / row
    const int2*  __restrict__ P = g_epack;

    float acc[4] = {0.f, 0.f, 0.f, 0.f};

    int e = beg;
#pragma unroll 1
    for (; e + 4 <= end; e += 4) {
        int2 p0 = __ldg(P + e + 0);
        int2 p1 = __ldg(P + e + 1);
        int2 p2 = __ldg(P + e + 2);
        int2 p3 = __ldg(P + e + 3);
        uint2 v0 = __ldg(T + (size_t)p0.x * 32 + lane);
        uint2 v1 = __ldg(T + (size_t)p1.x * 32 + lane);
        uint2 v2 = __ldg(T + (size_t)p2.x * 32 + lane);
        uint2 v3 = __ldg(T + (size_t)p3.x * 32 + lane);
        acc4(acc, v0, __int_as_float(p0.y));
        acc4(acc, v1, __int_as_float(p1.y));
        acc4(acc, v2, __int_as_float(p2.y));
        acc4(acc, v3, __int_as_float(p3.y));
    }
    for (; e < end; e++) {
        int2 p = __ldg(P + e);
        uint2 v = __ldg(T + (size_t)p.x * 32 + lane);
        acc4(acc, v, __int_as_float(p.y));
    }

    const float dd = g_dinv[d];
    acc4(acc, __ldg(T + (size_t)d * 32 + lane), dd * dd);

    __half2 o0 = __float22half2_rn(make_float2(acc[0], acc[1]));
    __half2 o1 = __float22half2_rn(make_float2(acc[2], acc[3]));
    uint2 o;
    o.x = *reinterpret_cast<uint32_t*>(&o0);
    o.y = *reinterpret_cast<uint32_t*>(&o1);
    reinterpret_cast<uint2*>(g_a1)[(size_t)d * 32 + lane] = o;
}

// ---------------- fp16 GEMM: C_f16[M,256] = A_f16[M,K] @ W_f16[K,256] (+bias,relu) --
#define ST_A   0
#define ST_B   16384
#define STAGE  32768
#define SM_TOTAL (2 * STAGE)   // 64 KB

__global__ __launch_bounds__(256, 2)
void tgemm_kernel(const __half* __restrict__ A,
                  const __half* __restrict__ W,
                  __half* __restrict__ C, int M, int K,
                  const float* __restrict__ bias, int dorelu)
{
    extern __shared__ char smem[];
    const uint32_t sb = smem_u32(smem);
    const int tid = threadIdx.x;
    const int wid = tid >> 5;
    const int lane = tid & 31;
    const int warp_m = wid & 3;
    const int warp_n = wid >> 2;
    const int row0 = blockIdx.x * 128;
    const int col0 = blockIdx.y * 128;

    float acc[2][8][4];
#pragma unroll
    for (int mt = 0; mt < 2; mt++)
#pragma unroll
        for (int nt = 0; nt < 8; nt++)
#pragma unroll
            for (int q = 0; q < 4; q++) acc[mt][nt][q] = 0.0f;

    const int lr   = lane & 7;
    const int lsel = lane >> 3;
    const int nch  = K >> 6;

    auto stage_load = [&](int c, int buf) {
        const int k0 = c << 6;
        const uint32_t base = sb + buf * STAGE;
#pragma unroll
        for (int i = 0; i < 4; i++) {
            const int idx = tid + (i << 8);
            const int row = idx >> 3;
            const int u   = idx & 7;
            const int grow = min(row0 + row, M - 1);
            cp16(base + ST_A + SWZ(row * 128 + u * 16),
                 A + (size_t)grow * K + k0 + u * 8);
        }
#pragma unroll
        for (int i = 0; i < 4; i++) {
            const int idx = tid + (i << 8);
            const int nr = idx >> 3;
            const int u  = idx & 7;
            cp16(base + ST_B + SWZ(nr * 128 + u * 16),
                 W + (size_t)(col0 + nr) * K + k0 + u * 8);
        }
        CP_COMMIT();
    };

    stage_load(0, 0);

    for (int c = 0; c < nch; c++) {
        if (c + 1 < nch) {
            stage_load(c + 1, (c + 1) & 1);
            asm volatile("cp.async.wait_group 1;" ::: "memory");
        } else {
            asm volatile("cp.async.wait_group 0;" ::: "memory");
        }
        __syncthreads();

        const uint32_t bufb = sb + (c & 1) * STAGE;
#pragma unroll
        for (int kk = 0; kk < 4; kk++) {
            const int kb = kk * 32 + (lsel & 2) * 8;
            uint32_t ah[8];
#pragma unroll
            for (int mt = 0; mt < 2; mt++) {
                const int arow = warp_m * 32 + mt * 16 + (lsel & 1) * 8 + lr;
                const uint32_t aoff = SWZ(arow * 128 + kb);
                ldsm_x4(bufb + ST_A + aoff, ah[mt*4+0], ah[mt*4+1], ah[mt*4+2], ah[mt*4+3]);
            }
            uint32_t bh[16];
#pragma unroll
            for (int p = 0; p < 4; p++) {
                const int brow = warp_n * 64 + p * 16 + (lsel >> 1) * 8 + lr;
                const uint32_t boff = SWZ(brow * 128 + kk * 32 + (lsel & 1) * 16);
                ldsm_x4(bufb + ST_B + boff, bh[p*4+0], bh[p*4+1], bh[p*4+2], bh[p*4+3]);
            }
#pragma unroll
            for (int mt = 0; mt < 2; mt++) {
#pragma unroll
                for (int nt = 0; nt < 8; nt++)
                    mma_f16(acc[mt][nt], &ah[mt*4], &bh[nt*2]);
            }
        }
        __syncthreads();
    }

    const int tr = lane >> 2;
    const int tc = (lane & 3) * 2;
#pragma unroll
    for (int mt = 0; mt < 2; mt++) {
#pragma unroll
        for (int nt = 0; nt < 8; nt++) {
            const int col = col0 + warp_n * 64 + nt * 8 + tc;
            float bx = 0.f, by = 0.f;
            if (bias) {
                float2 bb = *reinterpret_cast<const float2*>(bias + col);
                bx = bb.x; by = bb.y;
            }
            float v0 = acc[mt][nt][0] + bx, v1 = acc[mt][nt][1] + by;
            float v2 = acc[mt][nt][2] + bx, v3 = acc[mt][nt][3] + by;
            if (dorelu) {
                v0 = fmaxf(v0, 0.f); v1 = fmaxf(v1, 0.f);
                v2 = fmaxf(v2, 0.f); v3 = fmaxf(v3, 0.f);
            }
            const int r0 = row0 + warp_m * 32 + mt * 16 + tr;
            if (r0 < M) {
                __half2 v = __float22half2_rn(make_float2(v0, v1));
                *reinterpret_cast<__half2*>(C + (size_t)r0 * HDIM + col) = v;
            }
            if (r0 + 8 < M) {
                __half2 v = __float22half2_rn(make_float2(v2, v3));
                *reinterpret_cast<__half2*>(C + (size_t)(r0 + 8) * HDIM + col) = v;
            }
        }
    }
}

// ---------------- pull layer-2 fused with mean-pool (register accumulation) --------
__global__ __launch_bounds__(256)
void pull_sum_kernel(const float* __restrict__ b, int n, int nblocks)
{
    __shared__ float sacc[8][HDIM];
    const int tid  = threadIdx.x;
    const int wid  = tid >> 5;
    const int lane = tid & 31;

    float sum[8] = {0.f, 0.f, 0.f, 0.f, 0.f, 0.f, 0.f, 0.f};

    for (int d = blockIdx.x * 8 + wid; d < n; d += nblocks * 8) {
        float r[8];
        node_aggregate(d, lane, b, r);
#pragma unroll
        for (int j = 0; j < 8; j++) sum[j] += r[j];
    }

#pragma unroll
    for (int j = 0; j < 8; j++)
        sacc[wid][lane * 8 + j] = sum[j];
    __syncthreads();

    float t = 0.0f;
#pragma unroll
    for (int w = 0; w < 8; w++) t += sacc[w][tid];
    atomicAdd(&g_gv[tid], t);
}

// ---------------- final linear ----------------
__global__ void final_kernel(const float* __restrict__ Wl, const float* __restrict__ bl,
                             float* __restrict__ out, float invN)
{
    __shared__ float s[2];
    if (threadIdx.x < 2) s[threadIdx.x] = 0.0f;
    __syncthreads();
    const int j = threadIdx.x;
    const float gj = g_gv[j] * invN;
    atomicAdd(&s[0], gj * Wl[j * 2 + 0]);
    atomicAdd(&s[1], gj * Wl[j * 2 + 1]);
    __syncthreads();
    if (threadIdx.x < 2) out[threadIdx.x] = s[threadIdx.x] + bl[threadIdx.x];
}

// ---------------- launcher ----------------
extern "C" void kernel_launch(void* const* d_in, const int* in_sizes, int n_in,
                              void* d_out, int out_size)
{
    const float* x  = (const float*)d_in[0];
    const int*   ei = (const int*)  d_in[1];
    const float* W1 = (const float*)d_in[3];
    const float* b1 = (const float*)d_in[4];
    const float* W2 = (const float*)d_in[5];
    const float* b2 = (const float*)d_in[6];
    const float* Wl = (const float*)d_in[7];
    const float* bl = (const float*)d_in[8];
    float* out = (float*)d_out;

    const int n = in_sizes[0] / 128;   // 50000
    const int E = in_sizes[1] / 2;     // 800000

    const int* src = ei;
    const int* dst = ei + E;

    __half *th_ptr, *yh_ptr, *a1_ptr, *w1h16, *w2h16;
    cudaGetSymbolAddress((void**)&th_ptr, g_th);
    cudaGetSymbolAddress((void**)&yh_ptr, g_yh);
    cudaGetSymbolAddress((void**)&a1_ptr, g_a1);
    cudaGetSymbolAddress((void**)&w1h16, g_w1t_h16);
    cudaGetSymbolAddress((void**)&w2h16, g_w2t_h16);

    cudaFuncSetAttribute(tgemm_kernel, cudaFuncAttributeMaxDynamicSharedMemorySize, SM_TOTAL);

    const int nScanBlocks = (n + SCAN_B - 1) / SCAN_B;
    dim3 gemmGrid((n + 127) / 128, 2);
    const int pullBlocks = (n + 7) / 8;

    // ---- fork: CSR build on side stream, convall on main ----
    cudaEventRecord(g_side.fork, 0);
    cudaStreamWaitEvent(g_side.s, g_side.fork, 0);

    prep_kernel   <<<(n + 255) / 256, 256, 0, g_side.s>>>(n);
    deg_kernel    <<<(E + 255) / 256, 256, 0, g_side.s>>>(dst, E);
    scan1_kernel  <<<nScanBlocks, SCAN_B, 0, g_side.s>>>(n);
    scan2_kernel  <<<1, 512, 0, g_side.s>>>(nScanBlocks, n, E);
    scan3_kernel  <<<nScanBlocks, SCAN_B, 0, g_side.s>>>(n);
    scatter_kernel<<<(E + 255) / 256, 256, 0, g_side.s>>>(src, dst, E);
    cudaEventRecord(g_side.join, g_side.s);

    convall_kernel<<<(n * 32 + 255) / 256, 256>>>(x, W1, W2, n);

    // join: pull1' needs CSR + xh
    cudaStreamWaitEvent(0, g_side.join, 0);

    pull1_kernel<<<pullBlocks, 256>>>(n);                                    // agg1 = Â x
    tgemm_kernel<<<gemmGrid, 256, SM_TOTAL>>>(a1_ptr, w1h16, yh_ptr, n, 128, b1, 1);  // y
    tgemm_kernel<<<gemmGrid, 256, SM_TOTAL>>>(yh_ptr, w2h16, th_ptr, n, HDIM, nullptr, 0);
    pull_sum_kernel<<<PS_BLOCKS, 256>>>(b2, n, PS_BLOCKS);

    final_kernel<<<1, HDIM>>>(Wl, bl, out, 1.0f / (float)n);
}